// round 1
// baseline (speedup 1.0000x reference)
#include <cuda_runtime.h>
#include <cuda_bf16.h>
#include <math.h>

// Problem constants
#define DIMC   384
#define HEADS  8
#define CPH    48          // channels per head
#define WS     8
#define HH     256
#define WW     256
#define HW     65536       // 256*256
#define BATCH  2
#define QKV_M  1152        // 3*DIMC

// ---------------- scratch (device globals; no cudaMalloc allowed) -----------
__device__ float g_qkv[(size_t)BATCH * QKV_M * HW];   // 1x1-conv output (pre-dwconv), ~604 MB
__device__ float g_att[(size_t)BATCH * DIMC * HW];    // attention output, ~201 MB

// ---------------- SGEMM: C[M,N] = A[M,K] * B[K,N] (+bias), batched over z ---
// A: weights [M,K] row-major (shared across batch)
// B: per-batch [K,N] row-major, batch stride K*N
// C: per-batch [M,N] row-major, batch stride M*N
// M % 128 == 0, N % 128 == 0, K % 8 == 0 (all true here)
template <int WITH_BIAS>
__global__ __launch_bounds__(256) void sgemm128(
    const float* __restrict__ A, const float* __restrict__ Bg,
    float* __restrict__ Cg, int M, int N, int K,
    const float* __restrict__ bias)
{
    __shared__ __align__(16) float As[8][128];
    __shared__ __align__(16) float Bs[8][128];

    const int tid = threadIdx.x;
    const int bN  = blockIdx.x * 128;
    const int bM  = blockIdx.y * 128;
    const float* Bp = Bg + (size_t)blockIdx.z * K * N;
    float*       Cp = Cg + (size_t)blockIdx.z * M * N;

    const int aRow = tid >> 1;          // 0..127
    const int aCol = (tid & 1) << 2;    // 0 or 4
    const int bRow = tid >> 5;          // 0..7
    const int bCol = (tid & 31) << 2;   // 0..124

    const int ty = tid >> 4;            // 0..15 -> rows ty*8..ty*8+7
    const int tx = tid & 15;            // 0..15 -> cols tx*8..tx*8+7

    float acc[8][8];
#pragma unroll
    for (int i = 0; i < 8; i++)
#pragma unroll
        for (int j = 0; j < 8; j++) acc[i][j] = 0.f;

    for (int k0 = 0; k0 < K; k0 += 8) {
        float4 av = *reinterpret_cast<const float4*>(&A[(size_t)(bM + aRow) * K + k0 + aCol]);
        As[aCol + 0][aRow] = av.x;
        As[aCol + 1][aRow] = av.y;
        As[aCol + 2][aRow] = av.z;
        As[aCol + 3][aRow] = av.w;
        float4 bv = *reinterpret_cast<const float4*>(&Bp[(size_t)(k0 + bRow) * N + bN + bCol]);
        *reinterpret_cast<float4*>(&Bs[bRow][bCol]) = bv;
        __syncthreads();

#pragma unroll
        for (int kk = 0; kk < 8; ++kk) {
            float ra[8], rb[8];
            *reinterpret_cast<float4*>(&ra[0]) = *reinterpret_cast<const float4*>(&As[kk][ty * 8]);
            *reinterpret_cast<float4*>(&ra[4]) = *reinterpret_cast<const float4*>(&As[kk][ty * 8 + 4]);
            *reinterpret_cast<float4*>(&rb[0]) = *reinterpret_cast<const float4*>(&Bs[kk][tx * 8]);
            *reinterpret_cast<float4*>(&rb[4]) = *reinterpret_cast<const float4*>(&Bs[kk][tx * 8 + 4]);
#pragma unroll
            for (int i = 0; i < 8; i++)
#pragma unroll
                for (int j = 0; j < 8; j++) acc[i][j] += ra[i] * rb[j];
        }
        __syncthreads();
    }

#pragma unroll
    for (int i = 0; i < 8; i++) {
        const int m = bM + ty * 8 + i;
        const float bi = WITH_BIAS ? bias[m] : 0.f;
#pragma unroll
        for (int j = 0; j < 8; j += 4) {
            float4 v;
            v.x = acc[i][j + 0] + bi;
            v.y = acc[i][j + 1] + bi;
            v.z = acc[i][j + 2] + bi;
            v.w = acc[i][j + 3] + bi;
            *reinterpret_cast<float4*>(&Cp[(size_t)m * N + bN + tx * 8 + j]) = v;
        }
    }
}

// ---------------- Fused depthwise 3x3 + window channel-attention -------------
// One block per (window, head). Block = 256 threads.
// smem: halo [144][100] | qkv [144][65] (q:0-47,k:48-95,v:96-143) | attn [48][49] | dww [144*9]
#define S_HALO_STRIDE 100
#define S_QKV_STRIDE  65
#define S_ATTN_STRIDE 49
#define OFF_QKV  (144 * S_HALO_STRIDE)                 // 14400
#define OFF_ATTN (OFF_QKV + 144 * S_QKV_STRIDE)        // 14400 + 9360
#define OFF_DWW  (OFF_ATTN + 48 * S_ATTN_STRIDE)       // + 2352
#define SMEM_FLOATS (OFF_DWW + 144 * 9)                // + 1296 = 27408
#define SMEM_BYTES  (SMEM_FLOATS * 4)                  // 109632 B

__global__ __launch_bounds__(256) void win_attn_kernel(
    const float* __restrict__ qkv1,          // g_qkv [B, 1152, 256, 256]
    const float* __restrict__ dww,           // [1152, 1, 3, 3]
    const float* __restrict__ temperature,   // [8,1,1]
    float* __restrict__ outp)                // g_att [B, 384, 256, 256]
{
    extern __shared__ float sm[];
    float* s_halo = sm;
    float* s_qkv  = sm + OFF_QKV;
    float* s_attn = sm + OFF_ATTN;
    float* s_dww  = sm + OFF_DWW;

    const int tid  = threadIdx.x;
    const int wid  = blockIdx.x;           // 0..1023
    const int head = blockIdx.y;           // 0..7
    const int b    = blockIdx.z;           // 0..1
    const int wy = wid >> 5, wx = wid & 31;
    const int y0 = wy * 8 - 1, x0 = wx * 8 - 1;

    // ---- load halo (144 ch x 10x10) with zero padding ----
    const size_t chan_base = ((size_t)b * QKV_M) * HW;
    for (int e = tid; e < 144 * 100; e += 256) {
        const int l  = e / 100, p = e - l * 100;
        const int ly = p / 10,  lx = p - ly * 10;
        const int z  = l / 48,  cl = l - z * 48;
        const int gc = z * DIMC + head * CPH + cl;
        const int y  = y0 + ly, x = x0 + lx;
        float v = 0.f;
        if ((unsigned)y < (unsigned)HH && (unsigned)x < (unsigned)WW)
            v = qkv1[chan_base + (size_t)gc * HW + (y << 8) + x];
        s_halo[l * S_HALO_STRIDE + p] = v;
    }
    // ---- load depthwise weights ----
    for (int e = tid; e < 144 * 9; e += 256) {
        const int l = e / 9, kk = e - l * 9;
        const int z = l / 48, cl = l - z * 48;
        s_dww[e] = dww[(size_t)(z * DIMC + head * CPH + cl) * 9 + kk];
    }
    __syncthreads();

    // ---- depthwise 3x3 -> s_qkv[l][n], n = yy*8+xx ----
    {
        const int n = tid & 63;             // 0..63 spatial
        const int g = tid >> 6;             // 0..3
        const int yy = n >> 3, xx = n & 7;
#pragma unroll 4
        for (int i = 0; i < 36; i++) {
            const int l = g * 36 + i;
            const float* hb = s_halo + l * S_HALO_STRIDE + yy * 10 + xx;
            const float* wb = s_dww + l * 9;
            float s = 0.f;
#pragma unroll
            for (int dy = 0; dy < 3; dy++)
#pragma unroll
                for (int dx = 0; dx < 3; dx++)
                    s += hb[dy * 10 + dx] * wb[dy * 3 + dx];
            s_qkv[l * S_QKV_STRIDE + n] = s;
        }
    }
    __syncthreads();

    // ---- L2 normalize q,k rows (96 rows of 64) ----
    {
        const int warp = tid >> 5, lane = tid & 31;
        for (int r = warp; r < 96; r += 8) {
            float v0 = s_qkv[r * S_QKV_STRIDE + lane];
            float v1 = s_qkv[r * S_QKV_STRIDE + lane + 32];
            float s = v0 * v0 + v1 * v1;
#pragma unroll
            for (int off = 16; off; off >>= 1) s += __shfl_xor_sync(0xffffffffu, s, off);
            const float inv = 1.f / fmaxf(sqrtf(s), 1e-12f);
            s_qkv[r * S_QKV_STRIDE + lane]      = v0 * inv;
            s_qkv[r * S_QKV_STRIDE + lane + 32] = v1 * inv;
        }
    }
    __syncthreads();

    const float temp = __ldg(&temperature[head]);

    // ---- attn[c][d] = (q_c . k_d) * temp  (48x48, K=64) ----
    {
        const int ty = tid >> 4, tx = tid & 15;   // c = ty*3.., d = tx*3..
        float acc[3][3];
#pragma unroll
        for (int i = 0; i < 3; i++)
#pragma unroll
            for (int j = 0; j < 3; j++) acc[i][j] = 0.f;
        const float* qb = s_qkv + (ty * 3) * S_QKV_STRIDE;
        const float* kb = s_qkv + (48 + tx * 3) * S_QKV_STRIDE;
#pragma unroll 4
        for (int n = 0; n < 64; ++n) {
            const float q0 = qb[n], q1 = qb[S_QKV_STRIDE + n], q2 = qb[2 * S_QKV_STRIDE + n];
            const float k0 = kb[n], k1 = kb[S_QKV_STRIDE + n], k2 = kb[2 * S_QKV_STRIDE + n];
            acc[0][0] += q0 * k0; acc[0][1] += q0 * k1; acc[0][2] += q0 * k2;
            acc[1][0] += q1 * k0; acc[1][1] += q1 * k1; acc[1][2] += q1 * k2;
            acc[2][0] += q2 * k0; acc[2][1] += q2 * k1; acc[2][2] += q2 * k2;
        }
#pragma unroll
        for (int i = 0; i < 3; i++)
#pragma unroll
            for (int j = 0; j < 3; j++)
                s_attn[(ty * 3 + i) * S_ATTN_STRIDE + tx * 3 + j] = acc[i][j] * temp;
    }
    __syncthreads();

    // ---- softmax over d (48 rows of 48) ----
    {
        const int warp = tid >> 5, lane = tid & 31;
        for (int r = warp; r < 48; r += 8) {
            const float v0 = s_attn[r * S_ATTN_STRIDE + lane];
            const float v1 = (lane < 16) ? s_attn[r * S_ATTN_STRIDE + lane + 32] : -1e30f;
            float m = fmaxf(v0, v1);
#pragma unroll
            for (int off = 16; off; off >>= 1) m = fmaxf(m, __shfl_xor_sync(0xffffffffu, m, off));
            const float e0 = __expf(v0 - m);
            const float e1 = (lane < 16) ? __expf(v1 - m) : 0.f;
            float s = e0 + e1;
#pragma unroll
            for (int off = 16; off; off >>= 1) s += __shfl_xor_sync(0xffffffffu, s, off);
            const float inv = 1.f / s;
            s_attn[r * S_ATTN_STRIDE + lane] = e0 * inv;
            if (lane < 16) s_attn[r * S_ATTN_STRIDE + lane + 32] = e1 * inv;
        }
    }
    __syncthreads();

    // ---- out[c][n] = sum_d attn[c][d] * v[d][n]; write to global ----
    {
        const int ty = tid >> 4, tx = tid & 15;   // c = ty*3.., n = tx*4..
        float acc[3][4];
#pragma unroll
        for (int i = 0; i < 3; i++)
#pragma unroll
            for (int j = 0; j < 4; j++) acc[i][j] = 0.f;
#pragma unroll 4
        for (int d = 0; d < 48; ++d) {
            const float a0 = s_attn[(ty * 3 + 0) * S_ATTN_STRIDE + d];
            const float a1 = s_attn[(ty * 3 + 1) * S_ATTN_STRIDE + d];
            const float a2 = s_attn[(ty * 3 + 2) * S_ATTN_STRIDE + d];
            const float* vb = s_qkv + (96 + d) * S_QKV_STRIDE + tx * 4;
#pragma unroll
            for (int j = 0; j < 4; j++) {
                const float vv = vb[j];
                acc[0][j] += a0 * vv;
                acc[1][j] += a1 * vv;
                acc[2][j] += a2 * vv;
            }
        }
        const size_t ob = ((size_t)b * DIMC + head * CPH) * HW;
#pragma unroll
        for (int i = 0; i < 3; i++) {
            const int c = ty * 3 + i;
#pragma unroll
            for (int j = 0; j < 4; j++) {
                const int n = tx * 4 + j;
                const int yy = n >> 3, xx = n & 7;
                outp[ob + (size_t)c * HW + ((wy * 8 + yy) << 8) + (wx * 8 + xx)] = acc[i][j];
            }
        }
    }
}

// ---------------- launch ----------------------------------------------------
extern "C" void kernel_launch(void* const* d_in, const int* in_sizes, int n_in,
                              void* d_out, int out_size)
{
    const float* x      = (const float*)d_in[0];  // [2,384,256,256]
    const float* qkv_w  = (const float*)d_in[1];  // [1152,384]
    const float* dw_w   = (const float*)d_in[2];  // [1152,1,3,3]
    const float* temp   = (const float*)d_in[3];  // [8,1,1]
    const float* proj_w = (const float*)d_in[4];  // [384,384]
    const float* proj_b = (const float*)d_in[5];  // [384]
    float* out = (float*)d_out;

    float *qkv_buf = nullptr, *att_buf = nullptr;
    cudaGetSymbolAddress((void**)&qkv_buf, g_qkv);
    cudaGetSymbolAddress((void**)&att_buf, g_att);

    cudaFuncSetAttribute(win_attn_kernel,
                         cudaFuncAttributeMaxDynamicSharedMemorySize, SMEM_BYTES);

    // 1) qkv 1x1 conv: [1152,384] x [384,65536] per batch
    sgemm128<0><<<dim3(HW / 128, QKV_M / 128, BATCH), 256>>>(
        qkv_w, x, qkv_buf, QKV_M, HW, DIMC, nullptr);

    // 2) fused depthwise 3x3 + window channel attention
    win_attn_kernel<<<dim3(1024, HEADS, BATCH), 256, SMEM_BYTES>>>(
        qkv_buf, dw_w, temp, att_buf);

    // 3) project_out 1x1 conv with bias
    sgemm128<1><<<dim3(HW / 128, DIMC / 128, BATCH), 256>>>(
        proj_w, att_buf, out, DIMC, HW, DIMC, proj_b);
}

// round 3
// speedup vs baseline: 1.7092x; 1.7092x over previous
#include <cuda_runtime.h>
#include <cuda_bf16.h>
#include <cstdint>
#include <math.h>

// Problem constants
#define DIMC   384
#define HEADS  8
#define CPH    48
#define HH     256
#define WW     256
#define HW     65536
#define BATCH  2
#define QKV_M  1152        // 3*dim

// ---------------- scratch (device globals) ----------------------------------
__device__ float g_qkv[(size_t)BATCH * QKV_M * HW];           // [b][1152][hw] f32
__device__ float g_att[(size_t)BATCH * DIMC * HW];            // [b][384][hw]  f32
__device__ __nv_bfloat16 g_xt_hi[(size_t)BATCH * HW * DIMC];  // [b][hw][384]
__device__ __nv_bfloat16 g_xt_lo[(size_t)BATCH * HW * DIMC];
__device__ __nv_bfloat16 g_at_hi[(size_t)BATCH * HW * DIMC];
__device__ __nv_bfloat16 g_at_lo[(size_t)BATCH * HW * DIMC];
__device__ __nv_bfloat16 g_wq_hi[QKV_M * DIMC], g_wq_lo[QKV_M * DIMC];
__device__ __nv_bfloat16 g_wp_hi[DIMC * DIMC],  g_wp_lo[DIMC * DIMC];

// ---------------- helpers ----------------------------------------------------
__device__ __forceinline__ uint32_t smem_u32(const void* p) {
    uint32_t a;
    asm("{ .reg .u64 t; cvta.to.shared.u64 t, %1; cvt.u32.u64 %0, t; }" : "=r"(a) : "l"(p));
    return a;
}
#define CP_ASYNC16(saddr, gptr) \
    asm volatile("cp.async.cg.shared.global [%0], [%1], 16;" :: "r"(saddr), "l"(gptr))
#define CP_COMMIT() asm volatile("cp.async.commit_group;" ::: "memory")
#define CP_WAIT1()  asm volatile("cp.async.wait_group 1;" ::: "memory")

__device__ __forceinline__ void ldmx4(uint32_t* d, uint32_t addr) {
    asm volatile("ldmatrix.sync.aligned.m8n8.x4.shared.b16 {%0,%1,%2,%3}, [%4];"
                 : "=r"(d[0]), "=r"(d[1]), "=r"(d[2]), "=r"(d[3]) : "r"(addr));
}
__device__ __forceinline__ void mma16816(float* c, const uint32_t* a, uint32_t b0, uint32_t b1) {
    asm volatile("mma.sync.aligned.m16n8k16.row.col.f32.bf16.bf16.f32 "
                 "{%0,%1,%2,%3}, {%4,%5,%6,%7}, {%8,%9}, {%0,%1,%2,%3};"
                 : "+f"(c[0]), "+f"(c[1]), "+f"(c[2]), "+f"(c[3])
                 : "r"(a[0]), "r"(a[1]), "r"(a[2]), "r"(a[3]), "r"(b0), "r"(b1));
}
// Tile row layout: [128 rows][32 bf16] = row stride 64B, 4x 16B blocks per row.
// XOR swizzle keeps cp.async stores and every ldmatrix phase conflict-free.
__device__ __forceinline__ uint32_t swz(int r, int cb) {
    return (uint32_t)(r * 64 + ((cb ^ ((r >> 1) & 3)) << 4));
}

// ---------------- transpose + hi/lo bf16 split ------------------------------
__global__ __launch_bounds__(256) void transpose_split(
    const float* __restrict__ in, __nv_bfloat16* __restrict__ hi,
    __nv_bfloat16* __restrict__ lo, int C, int N)
{
    __shared__ float t[32][33];
    const int n0 = blockIdx.x * 32, c0 = blockIdx.y * 32;
    const size_t base = (size_t)blockIdx.z * C * N;
    const int tx = threadIdx.x & 31, ty = threadIdx.x >> 5;
#pragma unroll
    for (int i = 0; i < 4; i++) {
        const int c = ty + i * 8;
        t[c][tx] = in[base + (size_t)(c0 + c) * N + n0 + tx];
    }
    __syncthreads();
#pragma unroll
    for (int i = 0; i < 4; i++) {
        const int n = ty + i * 8;
        const float v = t[tx][n];
        const __nv_bfloat16 h = __float2bfloat16(v);
        const size_t o = base + (size_t)(n0 + n) * C + c0 + tx;
        hi[o] = h;
        lo[o] = __float2bfloat16(v - __bfloat162float(h));
    }
}

__global__ void split_w(const float* __restrict__ w, __nv_bfloat16* __restrict__ hi,
                        __nv_bfloat16* __restrict__ lo, int n)
{
    const int i = blockIdx.x * 256 + threadIdx.x;
    if (i < n) {
        const float v = w[i];
        const __nv_bfloat16 h = __float2bfloat16(v);
        hi[i] = h;
        lo[i] = __float2bfloat16(v - __bfloat162float(h));
    }
}

// ---------------- HMMA GEMM: C[M,N] = A[M,K] . B[N,K]^T ---------------------
// A: [M][K] bf16 hi/lo. B: per-batch [N][K] bf16 hi/lo. C: per-batch [M][N] f32.
// CTA tile 128(M) x 128(N), K-stage 32, double-buffered cp.async.
// smem stage layout: Ah @0, Al @8K, Bh @16K, Bl @24K; stage stride 32K.
#define HG_SMEM 65536

template <int WITH_BIAS>
__global__ __launch_bounds__(256) void hmma_gemm(
    const __nv_bfloat16* __restrict__ Ahi, const __nv_bfloat16* __restrict__ Alo,
    const __nv_bfloat16* __restrict__ Bhi, const __nv_bfloat16* __restrict__ Blo,
    float* __restrict__ Cg, int M, int N, int K, const float* __restrict__ bias)
{
    extern __shared__ char smem[];
    const uint32_t sb = smem_u32(smem);
    const int tid = threadIdx.x;
    const int wid = tid >> 5, lane = tid & 31;
    const int bM = blockIdx.x * 128;
    const int bN = blockIdx.y * 128;
    const size_t bb = (size_t)blockIdx.z * (size_t)N * K;
    float* Cp = Cg + (size_t)blockIdx.z * (size_t)M * N;

    const __nv_bfloat16* Ah = Ahi + (size_t)bM * K;
    const __nv_bfloat16* Al = Alo + (size_t)bM * K;
    const __nv_bfloat16* Bh = Bhi + bb + (size_t)bN * K;
    const __nv_bfloat16* Bl = Blo + bb + (size_t)bN * K;

    const int cb = tid & 3;         // 16B block within 32-elem k-slice
    const int r0 = tid >> 2;        // 0..63

    const int nst = K / 32;         // 12

    // ---- prologue: stage 0 ----
    {
        const int kk = cb * 8;
#pragma unroll
        for (int i = 0; i < 2; i++) {
            const int r = r0 + i * 64;
            const uint32_t so = swz(r, cb);
            CP_ASYNC16(sb + so,         Ah + (size_t)r * K + kk);
            CP_ASYNC16(sb + 8192 + so,  Al + (size_t)r * K + kk);
            CP_ASYNC16(sb + 16384 + so, Bh + (size_t)r * K + kk);
            CP_ASYNC16(sb + 24576 + so, Bl + (size_t)r * K + kk);
        }
        CP_COMMIT();
    }

    float acc[4][4][4];
#pragma unroll
    for (int i = 0; i < 4; i++)
#pragma unroll
        for (int j = 0; j < 4; j++)
#pragma unroll
            for (int k = 0; k < 4; k++) acc[i][j][k] = 0.f;

    // warp tiling: 2(M) x 4(N) warps; warp tile 64x32
    const int wm = (wid >> 2) * 64;
    const int wn = (wid & 3) * 32;
    // ldmatrix lane decomposition
    const int a_rbase = wm + ((lane >> 3) & 1) * 8 + (lane & 7);
    const int a_cbad  = lane >> 4;            // 0/1 -> k half
    const int b_rbase = wn + ((lane >> 4) & 1) * 8 + (lane & 7);
    const int b_cbad  = (lane >> 3) & 1;      // k half

    for (int s = 0; s < nst; s++) {
        if (s + 1 < nst) {
            const uint32_t st = sb + ((s + 1) & 1) * 32768;
            const int kk = (s + 1) * 32 + cb * 8;
#pragma unroll
            for (int i = 0; i < 2; i++) {
                const int r = r0 + i * 64;
                const uint32_t so = swz(r, cb);
                CP_ASYNC16(st + so,         Ah + (size_t)r * K + kk);
                CP_ASYNC16(st + 8192 + so,  Al + (size_t)r * K + kk);
                CP_ASYNC16(st + 16384 + so, Bh + (size_t)r * K + kk);
                CP_ASYNC16(st + 24576 + so, Bl + (size_t)r * K + kk);
            }
        }
        CP_COMMIT();
        CP_WAIT1();
        __syncthreads();

        const uint32_t st = sb + (s & 1) * 32768;
#pragma unroll
        for (int k16 = 0; k16 < 2; k16++) {
            uint32_t bhf[2][4], blf[2][4];
#pragma unroll
            for (int nh = 0; nh < 2; nh++) {
                const uint32_t ad = st + 16384 + swz(b_rbase + nh * 16, k16 * 2 + b_cbad);
                ldmx4(bhf[nh], ad);
                ldmx4(blf[nh], ad + 8192);
            }
#pragma unroll
            for (int mh = 0; mh < 4; mh++) {
                uint32_t ahf[4], alf[4];
                const uint32_t ad = st + swz(a_rbase + mh * 16, k16 * 2 + a_cbad);
                ldmx4(ahf, ad);
                ldmx4(alf, ad + 8192);
#pragma unroll
                for (int nb = 0; nb < 4; nb++) {
                    const uint32_t* fh = &bhf[nb >> 1][(nb & 1) * 2];
                    const uint32_t* fl = &blf[nb >> 1][(nb & 1) * 2];
                    mma16816(acc[mh][nb], ahf, fh[0], fh[1]);
                    mma16816(acc[mh][nb], ahf, fl[0], fl[1]);
                    mma16816(acc[mh][nb], alf, fh[0], fh[1]);
                }
            }
        }
        __syncthreads();
    }

    // ---- epilogue ----
    const int row0 = bM + wm + (lane >> 2);
    const int col0 = bN + wn + (lane & 3) * 2;
#pragma unroll
    for (int mh = 0; mh < 4; mh++) {
#pragma unroll
        for (int p = 0; p < 2; p++) {
            const int row = row0 + mh * 16 + p * 8;
            const float bi = WITH_BIAS ? __ldg(&bias[row]) : 0.f;
#pragma unroll
            for (int nb = 0; nb < 4; nb++) {
                float2 v;
                v.x = acc[mh][nb][p * 2 + 0] + bi;
                v.y = acc[mh][nb][p * 2 + 1] + bi;
                *reinterpret_cast<float2*>(&Cp[(size_t)row * N + col0 + nb * 8]) = v;
            }
        }
    }
}

// ---------------- Fused depthwise 3x3 + window channel-attention -------------
#define S_HALO_STRIDE 100
#define S_QKV_STRIDE  65
#define S_ATTN_STRIDE 49
#define OFF_QKV  (144 * S_HALO_STRIDE)
#define OFF_ATTN (OFF_QKV + 144 * S_QKV_STRIDE)
#define OFF_DWW  (OFF_ATTN + 48 * S_ATTN_STRIDE)
#define SMEM_FLOATS (OFF_DWW + 144 * 9)
#define SMEM_BYTES  (SMEM_FLOATS * 4)

__global__ __launch_bounds__(256) void win_attn_kernel(
    const float* __restrict__ qkv1,
    const float* __restrict__ dww,
    const float* __restrict__ temperature,
    float* __restrict__ outp)
{
    extern __shared__ float sm[];
    float* s_halo = sm;
    float* s_qkv  = sm + OFF_QKV;
    float* s_attn = sm + OFF_ATTN;
    float* s_dww  = sm + OFF_DWW;

    const int tid  = threadIdx.x;
    const int wid  = blockIdx.x;
    const int head = blockIdx.y;
    const int b    = blockIdx.z;
    const int wy = wid >> 5, wx = wid & 31;
    const int y0 = wy * 8 - 1, x0 = wx * 8 - 1;

    const size_t chan_base = ((size_t)b * QKV_M) * HW;
    for (int e = tid; e < 144 * 100; e += 256) {
        const int l  = e / 100, p = e - l * 100;
        const int ly = p / 10,  lx = p - ly * 10;
        const int z  = l / 48,  cl = l - z * 48;
        const int gc = z * DIMC + head * CPH + cl;
        const int y  = y0 + ly, x = x0 + lx;
        float v = 0.f;
        if ((unsigned)y < (unsigned)HH && (unsigned)x < (unsigned)WW)
            v = qkv1[chan_base + (size_t)gc * HW + (y << 8) + x];
        s_halo[l * S_HALO_STRIDE + p] = v;
    }
    for (int e = tid; e < 144 * 9; e += 256) {
        const int l = e / 9, kk = e - l * 9;
        const int z = l / 48, cl = l - z * 48;
        s_dww[e] = dww[(size_t)(z * DIMC + head * CPH + cl) * 9 + kk];
    }
    __syncthreads();

    {
        const int n = tid & 63;
        const int g = tid >> 6;
        const int yy = n >> 3, xx = n & 7;
#pragma unroll 4
        for (int i = 0; i < 36; i++) {
            const int l = g * 36 + i;
            const float* hb = s_halo + l * S_HALO_STRIDE + yy * 10 + xx;
            const float* wb = s_dww + l * 9;
            float s = 0.f;
#pragma unroll
            for (int dy = 0; dy < 3; dy++)
#pragma unroll
                for (int dx = 0; dx < 3; dx++)
                    s += hb[dy * 10 + dx] * wb[dy * 3 + dx];
            s_qkv[l * S_QKV_STRIDE + n] = s;
        }
    }
    __syncthreads();

    {
        const int warp = tid >> 5, lane = tid & 31;
        for (int r = warp; r < 96; r += 8) {
            float v0 = s_qkv[r * S_QKV_STRIDE + lane];
            float v1 = s_qkv[r * S_QKV_STRIDE + lane + 32];
            float s = v0 * v0 + v1 * v1;
#pragma unroll
            for (int off = 16; off; off >>= 1) s += __shfl_xor_sync(0xffffffffu, s, off);
            const float inv = 1.f / fmaxf(sqrtf(s), 1e-12f);
            s_qkv[r * S_QKV_STRIDE + lane]      = v0 * inv;
            s_qkv[r * S_QKV_STRIDE + lane + 32] = v1 * inv;
        }
    }
    __syncthreads();

    const float temp = __ldg(&temperature[head]);

    {
        const int ty = tid >> 4, tx = tid & 15;
        float acc[3][3];
#pragma unroll
        for (int i = 0; i < 3; i++)
#pragma unroll
            for (int j = 0; j < 3; j++) acc[i][j] = 0.f;
        const float* qb = s_qkv + (ty * 3) * S_QKV_STRIDE;
        const float* kb = s_qkv + (48 + tx * 3) * S_QKV_STRIDE;
#pragma unroll 4
        for (int n = 0; n < 64; ++n) {
            const float q0 = qb[n], q1 = qb[S_QKV_STRIDE + n], q2 = qb[2 * S_QKV_STRIDE + n];
            const float k0 = kb[n], k1 = kb[S_QKV_STRIDE + n], k2 = kb[2 * S_QKV_STRIDE + n];
            acc[0][0] += q0 * k0; acc[0][1] += q0 * k1; acc[0][2] += q0 * k2;
            acc[1][0] += q1 * k0; acc[1][1] += q1 * k1; acc[1][2] += q1 * k2;
            acc[2][0] += q2 * k0; acc[2][1] += q2 * k1; acc[2][2] += q2 * k2;
        }
#pragma unroll
        for (int i = 0; i < 3; i++)
#pragma unroll
            for (int j = 0; j < 3; j++)
                s_attn[(ty * 3 + i) * S_ATTN_STRIDE + tx * 3 + j] = acc[i][j] * temp;
    }
    __syncthreads();

    {
        const int warp = tid >> 5, lane = tid & 31;
        for (int r = warp; r < 48; r += 8) {
            const float v0 = s_attn[r * S_ATTN_STRIDE + lane];
            const float v1 = (lane < 16) ? s_attn[r * S_ATTN_STRIDE + lane + 32] : -1e30f;
            float m = fmaxf(v0, v1);
#pragma unroll
            for (int off = 16; off; off >>= 1) m = fmaxf(m, __shfl_xor_sync(0xffffffffu, m, off));
            const float e0 = __expf(v0 - m);
            const float e1 = (lane < 16) ? __expf(v1 - m) : 0.f;
            float s = e0 + e1;
#pragma unroll
            for (int off = 16; off; off >>= 1) s += __shfl_xor_sync(0xffffffffu, s, off);
            const float inv = 1.f / s;
            s_attn[r * S_ATTN_STRIDE + lane] = e0 * inv;
            if (lane < 16) s_attn[r * S_ATTN_STRIDE + lane + 32] = e1 * inv;
        }
    }
    __syncthreads();

    {
        const int ty = tid >> 4, tx = tid & 15;
        float acc[3][4];
#pragma unroll
        for (int i = 0; i < 3; i++)
#pragma unroll
            for (int j = 0; j < 4; j++) acc[i][j] = 0.f;
#pragma unroll 4
        for (int d = 0; d < 48; ++d) {
            const float a0 = s_attn[(ty * 3 + 0) * S_ATTN_STRIDE + d];
            const float a1 = s_attn[(ty * 3 + 1) * S_ATTN_STRIDE + d];
            const float a2 = s_attn[(ty * 3 + 2) * S_ATTN_STRIDE + d];
            const float* vb = s_qkv + (96 + d) * S_QKV_STRIDE + tx * 4;
#pragma unroll
            for (int j = 0; j < 4; j++) {
                const float vv = vb[j];
                acc[0][j] += a0 * vv;
                acc[1][j] += a1 * vv;
                acc[2][j] += a2 * vv;
            }
        }
        const size_t ob = ((size_t)b * DIMC + head * CPH) * HW;
#pragma unroll
        for (int i = 0; i < 3; i++) {
            const int c = ty * 3 + i;
#pragma unroll
            for (int j = 0; j < 4; j++) {
                const int n = tx * 4 + j;
                const int yy = n >> 3, xx = n & 7;
                outp[ob + (size_t)c * HW + ((wy * 8 + yy) << 8) + (wx * 8 + xx)] = acc[i][j];
            }
        }
    }
}

// ---------------- launch ----------------------------------------------------
extern "C" void kernel_launch(void* const* d_in, const int* in_sizes, int n_in,
                              void* d_out, int out_size)
{
    const float* x      = (const float*)d_in[0];
    const float* qkv_w  = (const float*)d_in[1];
    const float* dw_w   = (const float*)d_in[2];
    const float* temp   = (const float*)d_in[3];
    const float* proj_w = (const float*)d_in[4];
    const float* proj_b = (const float*)d_in[5];
    float* out = (float*)d_out;

    float *qkv_buf, *att_buf;
    __nv_bfloat16 *xt_hi, *xt_lo, *at_hi, *at_lo, *wq_hi, *wq_lo, *wp_hi, *wp_lo;
    cudaGetSymbolAddress((void**)&qkv_buf, g_qkv);
    cudaGetSymbolAddress((void**)&att_buf, g_att);
    cudaGetSymbolAddress((void**)&xt_hi, g_xt_hi);
    cudaGetSymbolAddress((void**)&xt_lo, g_xt_lo);
    cudaGetSymbolAddress((void**)&at_hi, g_at_hi);
    cudaGetSymbolAddress((void**)&at_lo, g_at_lo);
    cudaGetSymbolAddress((void**)&wq_hi, g_wq_hi);
    cudaGetSymbolAddress((void**)&wq_lo, g_wq_lo);
    cudaGetSymbolAddress((void**)&wp_hi, g_wp_hi);
    cudaGetSymbolAddress((void**)&wp_lo, g_wp_lo);

    cudaFuncSetAttribute(win_attn_kernel, cudaFuncAttributeMaxDynamicSharedMemorySize, SMEM_BYTES);
    cudaFuncSetAttribute(hmma_gemm<0>, cudaFuncAttributeMaxDynamicSharedMemorySize, HG_SMEM);
    cudaFuncSetAttribute(hmma_gemm<1>, cudaFuncAttributeMaxDynamicSharedMemorySize, HG_SMEM);

    // weight splits
    split_w<<<(QKV_M * DIMC + 255) / 256, 256>>>(qkv_w, wq_hi, wq_lo, QKV_M * DIMC);
    split_w<<<(DIMC * DIMC + 255) / 256, 256>>>(proj_w, wp_hi, wp_lo, DIMC * DIMC);

    // x -> transposed hi/lo bf16 [b][hw][384]
    transpose_split<<<dim3(HW / 32, DIMC / 32, BATCH), 256>>>(x, xt_hi, xt_lo, DIMC, HW);

    // qkv = W_qkv . x   -> g_qkv [b][1152][hw] f32
    hmma_gemm<0><<<dim3(QKV_M / 128, HW / 128, BATCH), 256, HG_SMEM>>>(
        wq_hi, wq_lo, xt_hi, xt_lo, qkv_buf, QKV_M, HW, DIMC, nullptr);

    // fused dwconv + window channel attention -> g_att [b][384][hw] f32
    win_attn_kernel<<<dim3(1024, HEADS, BATCH), 256, SMEM_BYTES>>>(qkv_buf, dw_w, temp, att_buf);

    // att -> transposed hi/lo bf16
    transpose_split<<<dim3(HW / 32, DIMC / 32, BATCH), 256>>>(att_buf, at_hi, at_lo, DIMC, HW);

    // out = W_proj . att + b
    hmma_gemm<1><<<dim3(DIMC / 128, HW / 128, BATCH), 256, HG_SMEM>>>(
        wp_hi, wp_lo, at_hi, at_lo, out, DIMC, HW, DIMC, proj_b);
}

// round 5
// speedup vs baseline: 2.0872x; 1.2211x over previous
#include <cuda_runtime.h>
#include <cuda_bf16.h>
#include <cstdint>
#include <math.h>

// Problem constants
#define DIMC   384
#define HEADS  8
#define CPH    48
#define HH     256
#define WW     256
#define HW     65536
#define BATCH  2
#define QKV_M  1152        // 3*dim

// ---------------- scratch (device globals) ----------------------------------
__device__ float g_qkv[(size_t)BATCH * QKV_M * HW];           // [b][1152][hw] f32
__device__ __nv_bfloat16 g_xt_hi[(size_t)BATCH * HW * DIMC];  // [b][hw][384]
__device__ __nv_bfloat16 g_xt_lo[(size_t)BATCH * HW * DIMC];
__device__ __nv_bfloat16 g_at_hi[(size_t)BATCH * HW * DIMC];
__device__ __nv_bfloat16 g_at_lo[(size_t)BATCH * HW * DIMC];
__device__ __nv_bfloat16 g_wq_hi[QKV_M * DIMC], g_wq_lo[QKV_M * DIMC];
__device__ __nv_bfloat16 g_wp_hi[DIMC * DIMC],  g_wp_lo[DIMC * DIMC];

// ---------------- helpers ----------------------------------------------------
__device__ __forceinline__ uint32_t smem_u32(const void* p) {
    uint32_t a;
    asm("{ .reg .u64 t; cvta.to.shared.u64 t, %1; cvt.u32.u64 %0, t; }" : "=r"(a) : "l"(p));
    return a;
}
#define CP_ASYNC16(saddr, gptr) \
    asm volatile("cp.async.cg.shared.global [%0], [%1], 16;" :: "r"(saddr), "l"(gptr))
#define CP_COMMIT() asm volatile("cp.async.commit_group;" ::: "memory")
#define CP_WAIT2()  asm volatile("cp.async.wait_group 2;" ::: "memory")

__device__ __forceinline__ void ldmx4(uint32_t* d, uint32_t addr) {
    asm volatile("ldmatrix.sync.aligned.m8n8.x4.shared.b16 {%0,%1,%2,%3}, [%4];"
                 : "=r"(d[0]), "=r"(d[1]), "=r"(d[2]), "=r"(d[3]) : "r"(addr));
}
__device__ __forceinline__ void mma16816(float* c, const uint32_t* a, uint32_t b0, uint32_t b1) {
    asm volatile("mma.sync.aligned.m16n8k16.row.col.f32.bf16.bf16.f32 "
                 "{%0,%1,%2,%3}, {%4,%5,%6,%7}, {%8,%9}, {%0,%1,%2,%3};"
                 : "+f"(c[0]), "+f"(c[1]), "+f"(c[2]), "+f"(c[3])
                 : "r"(a[0]), "r"(a[1]), "r"(a[2]), "r"(a[3]), "r"(b0), "r"(b1));
}
// Tile row layout: [128 rows][32 bf16] = row stride 64B, 4x 16B blocks per row.
__device__ __forceinline__ uint32_t swz(int r, int cb) {
    return (uint32_t)(r * 64 + ((cb ^ ((r >> 1) & 3)) << 4));
}

// ---------------- transpose + hi/lo bf16 split (for x only) ------------------
__global__ __launch_bounds__(256) void transpose_split(
    const float* __restrict__ in, __nv_bfloat16* __restrict__ hi,
    __nv_bfloat16* __restrict__ lo, int C, int N)
{
    __shared__ float t[32][33];
    const int n0 = blockIdx.x * 32, c0 = blockIdx.y * 32;
    const size_t base = (size_t)blockIdx.z * C * N;
    const int tx = threadIdx.x & 31, ty = threadIdx.x >> 5;
#pragma unroll
    for (int i = 0; i < 4; i++) {
        const int c = ty + i * 8;
        t[c][tx] = in[base + (size_t)(c0 + c) * N + n0 + tx];
    }
    __syncthreads();
#pragma unroll
    for (int i = 0; i < 4; i++) {
        const int n = ty + i * 8;
        const float v = t[tx][n];
        const __nv_bfloat16 h = __float2bfloat16(v);
        const size_t o = base + (size_t)(n0 + n) * C + c0 + tx;
        hi[o] = h;
        lo[o] = __float2bfloat16(v - __bfloat162float(h));
    }
}

__global__ void split_w(const float* __restrict__ w, __nv_bfloat16* __restrict__ hi,
                        __nv_bfloat16* __restrict__ lo, int n)
{
    const int i = blockIdx.x * 256 + threadIdx.x;
    if (i < n) {
        const float v = w[i];
        const __nv_bfloat16 h = __float2bfloat16(v);
        hi[i] = h;
        lo[i] = __float2bfloat16(v - __bfloat162float(h));
    }
}

// ---------------- HMMA GEMM: C[M,N] = A[M,K] . B[N,K]^T ---------------------
// CTA tile 128x128, K-stage 32, 3-stage cp.async pipeline.
// stage layout: Ah @0, Al @8K, Bh @16K, Bl @24K; stage stride 32K.
#define HG_SMEM 98304

template <int WITH_BIAS>
__global__ __launch_bounds__(256) void hmma_gemm(
    const __nv_bfloat16* __restrict__ Ahi, const __nv_bfloat16* __restrict__ Alo,
    const __nv_bfloat16* __restrict__ Bhi, const __nv_bfloat16* __restrict__ Blo,
    float* __restrict__ Cg, int M, int N, int K, const float* __restrict__ bias)
{
    extern __shared__ char smem[];
    const uint32_t sb = smem_u32(smem);
    const int tid = threadIdx.x;
    const int wid = tid >> 5, lane = tid & 31;
    const int bM = blockIdx.x * 128;
    const int bN = blockIdx.y * 128;
    const size_t bb = (size_t)blockIdx.z * (size_t)N * K;
    float* Cp = Cg + (size_t)blockIdx.z * (size_t)M * N;

    const __nv_bfloat16* Ah = Ahi + (size_t)bM * K;
    const __nv_bfloat16* Al = Alo + (size_t)bM * K;
    const __nv_bfloat16* Bh = Bhi + bb + (size_t)bN * K;
    const __nv_bfloat16* Bl = Blo + bb + (size_t)bN * K;

    const int cb = tid & 3;         // 16B block within 32-elem k-slice
    const int r0 = tid >> 2;        // 0..63
    const int nst = K / 32;         // 12

    // ---- prologue: fill stages 0,1 ----
#pragma unroll
    for (int ps = 0; ps < 2; ps++) {
        const uint32_t st = sb + ps * 32768;
        const int kk = ps * 32 + cb * 8;
#pragma unroll
        for (int i = 0; i < 2; i++) {
            const int r = r0 + i * 64;
            const uint32_t so = swz(r, cb);
            CP_ASYNC16(st + so,         Ah + (size_t)r * K + kk);
            CP_ASYNC16(st + 8192 + so,  Al + (size_t)r * K + kk);
            CP_ASYNC16(st + 16384 + so, Bh + (size_t)r * K + kk);
            CP_ASYNC16(st + 24576 + so, Bl + (size_t)r * K + kk);
        }
        CP_COMMIT();
    }

    float acc[4][4][4];
#pragma unroll
    for (int i = 0; i < 4; i++)
#pragma unroll
        for (int j = 0; j < 4; j++)
#pragma unroll
            for (int k = 0; k < 4; k++) acc[i][j][k] = 0.f;

    // warp tiling: 2(M) x 4(N) warps; warp tile 64x32
    const int wm = (wid >> 2) * 64;
    const int wn = (wid & 3) * 32;
    const int a_rbase = wm + ((lane >> 3) & 1) * 8 + (lane & 7);
    const int a_cbad  = lane >> 4;
    const int b_rbase = wn + ((lane >> 4) & 1) * 8 + (lane & 7);
    const int b_cbad  = (lane >> 3) & 1;

    int sidx = 0;   // buffer index of stage s
    for (int s = 0; s < nst; s++) {
        if (s + 2 < nst) {
            int fi = sidx + 2; if (fi >= 3) fi -= 3;
            const uint32_t st = sb + fi * 32768;
            const int kk = (s + 2) * 32 + cb * 8;
#pragma unroll
            for (int i = 0; i < 2; i++) {
                const int r = r0 + i * 64;
                const uint32_t so = swz(r, cb);
                CP_ASYNC16(st + so,         Ah + (size_t)r * K + kk);
                CP_ASYNC16(st + 8192 + so,  Al + (size_t)r * K + kk);
                CP_ASYNC16(st + 16384 + so, Bh + (size_t)r * K + kk);
                CP_ASYNC16(st + 24576 + so, Bl + (size_t)r * K + kk);
            }
        }
        CP_COMMIT();
        CP_WAIT2();
        __syncthreads();

        const uint32_t st = sb + sidx * 32768;
#pragma unroll
        for (int k16 = 0; k16 < 2; k16++) {
            uint32_t bhf[2][4], blf[2][4];
#pragma unroll
            for (int nh = 0; nh < 2; nh++) {
                const uint32_t ad = st + 16384 + swz(b_rbase + nh * 16, k16 * 2 + b_cbad);
                ldmx4(bhf[nh], ad);
                ldmx4(blf[nh], ad + 8192);
            }
#pragma unroll
            for (int mh = 0; mh < 4; mh++) {
                uint32_t ahf[4], alf[4];
                const uint32_t ad = st + swz(a_rbase + mh * 16, k16 * 2 + a_cbad);
                ldmx4(ahf, ad);
                ldmx4(alf, ad + 8192);
#pragma unroll
                for (int nb = 0; nb < 4; nb++) {
                    const uint32_t* fh = &bhf[nb >> 1][(nb & 1) * 2];
                    const uint32_t* fl = &blf[nb >> 1][(nb & 1) * 2];
                    mma16816(acc[mh][nb], ahf, fh[0], fh[1]);
                    mma16816(acc[mh][nb], ahf, fl[0], fl[1]);
                    mma16816(acc[mh][nb], alf, fh[0], fh[1]);
                }
            }
        }
        __syncthreads();
        if (++sidx == 3) sidx = 0;
    }

    // ---- epilogue ----
    const int row0 = bM + wm + (lane >> 2);
    const int col0 = bN + wn + (lane & 3) * 2;
#pragma unroll
    for (int mh = 0; mh < 4; mh++) {
#pragma unroll
        for (int p = 0; p < 2; p++) {
            const int row = row0 + mh * 16 + p * 8;
            const float bi = WITH_BIAS ? __ldg(&bias[row]) : 0.f;
#pragma unroll
            for (int nb = 0; nb < 4; nb++) {
                float2 v;
                v.x = acc[mh][nb][p * 2 + 0] + bi;
                v.y = acc[mh][nb][p * 2 + 1] + bi;
                *reinterpret_cast<float2*>(&Cp[(size_t)row * N + col0 + nb * 8]) = v;
            }
        }
    }
}

// ---------------- Fused dwconv 3x3 + window channel-attention ---------------
// One block per (window, head). 256 threads. Phased dwconv (q,k,v) with one
// 48-channel halo buffer. Output written directly as bf16 hi/lo [b][hw][384].
#define S_HALO_STRIDE 100
#define S_QKV_STRIDE  65
#define S_ATTN_STRIDE 49
#define OFF_HALO 0
#define OFF_QKV  (48 * S_HALO_STRIDE)                  // 4800
#define OFF_ATTN (OFF_QKV + 144 * S_QKV_STRIDE)        // +9360
#define OFF_DWW  (OFF_ATTN + 48 * S_ATTN_STRIDE)       // +2352
#define SMEM_FLOATS (OFF_DWW + 144 * 9)                // +1296 = 17808
#define SMEM_BYTES  (SMEM_FLOATS * 4)                  // 71232

__global__ __launch_bounds__(256) void win_attn_kernel(
    const float* __restrict__ qkv1,          // [b][1152][hw] f32
    const float* __restrict__ dww,           // [1152][9]
    const float* __restrict__ temperature,   // [8]
    __nv_bfloat16* __restrict__ out_hi,      // [b][hw][384]
    __nv_bfloat16* __restrict__ out_lo)
{
    extern __shared__ float sm[];
    float* s_halo = sm + OFF_HALO;           // 48 x 100 (reused as out 48 x 65)
    float* s_qkv  = sm + OFF_QKV;            // 144 x 65
    float* s_attn = sm + OFF_ATTN;           // 48 x 49
    float* s_dww  = sm + OFF_DWW;            // 144 x 9

    const int tid  = threadIdx.x;
    const int wid  = blockIdx.x;
    const int head = blockIdx.y;
    const int b    = blockIdx.z;
    const int wy = wid >> 5, wx = wid & 31;
    const int y0 = wy * 8 - 1, x0 = wx * 8 - 1;
    const size_t chan_base = ((size_t)b * QKV_M) * HW;

    // depthwise weights for all 3 z-groups of this head
    for (int e = tid; e < 144 * 9; e += 256) {
        const int l = e / 9, kk = e - l * 9;
        const int z = l / 48, cl = l - z * 48;
        s_dww[e] = dww[(size_t)(z * DIMC + head * CPH + cl) * 9 + kk];
    }

    const int dn = tid & 63;                 // dwconv spatial
    const int dg = tid >> 6;                 // 0..3
    const int dyy = dn >> 3, dxx = dn & 7;

    // ---- phases q (z=0), k (z=1): halo load + dwconv ----
#pragma unroll 1
    for (int z = 0; z < 2; z++) {
        for (int e = tid; e < 4800; e += 256) {
            const int l = e / 100, p = e - l * 100;
            const int ly = p / 10, lx = p - ly * 10;
            const int gc = z * DIMC + head * CPH + l;
            const int y = y0 + ly, x = x0 + lx;
            float v = 0.f;
            if ((unsigned)y < (unsigned)HH && (unsigned)x < (unsigned)WW)
                v = qkv1[chan_base + (size_t)gc * HW + (y << 8) + x];
            s_halo[l * S_HALO_STRIDE + p] = v;
        }
        __syncthreads();
#pragma unroll 3
        for (int i = 0; i < 12; i++) {
            const int cl = dg * 12 + i;
            const float* hb = s_halo + cl * S_HALO_STRIDE + dyy * 10 + dxx;
            const float* wb = s_dww + (z * 48 + cl) * 9;
            float s = 0.f;
#pragma unroll
            for (int dy = 0; dy < 3; dy++)
#pragma unroll
                for (int dx = 0; dx < 3; dx++)
                    s += hb[dy * 10 + dx] * wb[dy * 3 + dx];
            s_qkv[(z * 48 + cl) * S_QKV_STRIDE + dn] = s;
        }
        __syncthreads();
    }

    // ---- halo load for v (z=2); latency hidden behind QK/softmax ----
    for (int e = tid; e < 4800; e += 256) {
        const int l = e / 100, p = e - l * 100;
        const int ly = p / 10, lx = p - ly * 10;
        const int gc = 2 * DIMC + head * CPH + l;
        const int y = y0 + ly, x = x0 + lx;
        float v = 0.f;
        if ((unsigned)y < (unsigned)HH && (unsigned)x < (unsigned)WW)
            v = qkv1[chan_base + (size_t)gc * HW + (y << 8) + x];
        s_halo[l * S_HALO_STRIDE + p] = v;
    }

    // ---- L2 normalize q,k rows (96 rows of 64) ----
    {
        const int warp = tid >> 5, lane = tid & 31;
        for (int r = warp; r < 96; r += 8) {
            float v0 = s_qkv[r * S_QKV_STRIDE + lane];
            float v1 = s_qkv[r * S_QKV_STRIDE + lane + 32];
            float s = v0 * v0 + v1 * v1;
#pragma unroll
            for (int off = 16; off; off >>= 1) s += __shfl_xor_sync(0xffffffffu, s, off);
            const float inv = 1.f / fmaxf(sqrtf(s), 1e-12f);
            s_qkv[r * S_QKV_STRIDE + lane]      = v0 * inv;
            s_qkv[r * S_QKV_STRIDE + lane + 32] = v1 * inv;
        }
    }
    __syncthreads();

    const float temp = __ldg(&temperature[head]);

    // ---- attn[c][d] = (q_c . k_d) * temp  (48x48, K=64) ----
    {
        const int ty = tid >> 4, tx = tid & 15;
        float acc[3][3];
#pragma unroll
        for (int i = 0; i < 3; i++)
#pragma unroll
            for (int j = 0; j < 3; j++) acc[i][j] = 0.f;
        const float* qb = s_qkv + (ty * 3) * S_QKV_STRIDE;
        const float* kb = s_qkv + (48 + tx * 3) * S_QKV_STRIDE;
#pragma unroll 4
        for (int n = 0; n < 64; ++n) {
            const float q0 = qb[n], q1 = qb[S_QKV_STRIDE + n], q2 = qb[2 * S_QKV_STRIDE + n];
            const float k0 = kb[n], k1 = kb[S_QKV_STRIDE + n], k2 = kb[2 * S_QKV_STRIDE + n];
            acc[0][0] += q0 * k0; acc[0][1] += q0 * k1; acc[0][2] += q0 * k2;
            acc[1][0] += q1 * k0; acc[1][1] += q1 * k1; acc[1][2] += q1 * k2;
            acc[2][0] += q2 * k0; acc[2][1] += q2 * k1; acc[2][2] += q2 * k2;
        }
#pragma unroll
        for (int i = 0; i < 3; i++)
#pragma unroll
            for (int j = 0; j < 3; j++)
                s_attn[(ty * 3 + i) * S_ATTN_STRIDE + tx * 3 + j] = acc[i][j] * temp;
    }
    __syncthreads();

    // ---- softmax over d ----
    {
        const int warp = tid >> 5, lane = tid & 31;
        for (int r = warp; r < 48; r += 8) {
            const float v0 = s_attn[r * S_ATTN_STRIDE + lane];
            const float v1 = (lane < 16) ? s_attn[r * S_ATTN_STRIDE + lane + 32] : -1e30f;
            float m = fmaxf(v0, v1);
#pragma unroll
            for (int off = 16; off; off >>= 1) m = fmaxf(m, __shfl_xor_sync(0xffffffffu, m, off));
            const float e0 = __expf(v0 - m);
            const float e1 = (lane < 16) ? __expf(v1 - m) : 0.f;
            float s = e0 + e1;
#pragma unroll
            for (int off = 16; off; off >>= 1) s += __shfl_xor_sync(0xffffffffu, s, off);
            const float inv = 1.f / s;
            s_attn[r * S_ATTN_STRIDE + lane] = e0 * inv;
            if (lane < 16) s_attn[r * S_ATTN_STRIDE + lane + 32] = e1 * inv;
        }
    }
    __syncthreads();

    // ---- dwconv v (z=2): s_halo -> s_qkv rows 96..143 ----
#pragma unroll 3
    for (int i = 0; i < 12; i++) {
        const int cl = dg * 12 + i;
        const float* hb = s_halo + cl * S_HALO_STRIDE + dyy * 10 + dxx;
        const float* wb = s_dww + (2 * 48 + cl) * 9;
        float s = 0.f;
#pragma unroll
        for (int dy = 0; dy < 3; dy++)
#pragma unroll
            for (int dx = 0; dx < 3; dx++)
                s += hb[dy * 10 + dx] * wb[dy * 3 + dx];
        s_qkv[(96 + cl) * S_QKV_STRIDE + dn] = s;
    }
    __syncthreads();

    // ---- out[c][n] = sum_d attn[c][d] * v[d][n] -> s_out (reuse s_halo) ----
    float* s_out = s_halo;   // 48 x 65
    {
        const int ty = tid >> 4, tx = tid & 15;
        float acc[3][4];
#pragma unroll
        for (int i = 0; i < 3; i++)
#pragma unroll
            for (int j = 0; j < 4; j++) acc[i][j] = 0.f;
#pragma unroll 4
        for (int d = 0; d < 48; ++d) {
            const float a0 = s_attn[(ty * 3 + 0) * S_ATTN_STRIDE + d];
            const float a1 = s_attn[(ty * 3 + 1) * S_ATTN_STRIDE + d];
            const float a2 = s_attn[(ty * 3 + 2) * S_ATTN_STRIDE + d];
            const float* vb = s_qkv + (96 + d) * S_QKV_STRIDE + tx * 4;
#pragma unroll
            for (int j = 0; j < 4; j++) {
                const float vv = vb[j];
                acc[0][j] += a0 * vv;
                acc[1][j] += a1 * vv;
                acc[2][j] += a2 * vv;
            }
        }
#pragma unroll
        for (int i = 0; i < 3; i++)
#pragma unroll
            for (int j = 0; j < 4; j++)
                s_out[(ty * 3 + i) * S_QKV_STRIDE + tx * 4 + j] = acc[i][j];
    }
    __syncthreads();

    // ---- write bf16 hi/lo to [b][hw][384] (fused transpose + split) --------
    for (int e = tid; e < 3072; e += 256) {
        const int c = e % 48;
        const int n = e / 48;
        const float v = s_out[c * S_QKV_STRIDE + n];
        const int yy = n >> 3, xx = n & 7;
        const int hw = ((wy * 8 + yy) << 8) + wx * 8 + xx;
        const size_t off = ((size_t)b * HW + hw) * DIMC + head * CPH + c;
        const __nv_bfloat16 h = __float2bfloat16(v);
        out_hi[off] = h;
        out_lo[off] = __float2bfloat16(v - __bfloat162float(h));
    }
}

// ---------------- launch ----------------------------------------------------
extern "C" void kernel_launch(void* const* d_in, const int* in_sizes, int n_in,
                              void* d_out, int out_size)
{
    const float* x      = (const float*)d_in[0];
    const float* qkv_w  = (const float*)d_in[1];
    const float* dw_w   = (const float*)d_in[2];
    const float* temp   = (const float*)d_in[3];
    const float* proj_w = (const float*)d_in[4];
    const float* proj_b = (const float*)d_in[5];
    float* out = (float*)d_out;

    float *qkv_buf;
    __nv_bfloat16 *xt_hi, *xt_lo, *at_hi, *at_lo, *wq_hi, *wq_lo, *wp_hi, *wp_lo;
    cudaGetSymbolAddress((void**)&qkv_buf, g_qkv);
    cudaGetSymbolAddress((void**)&xt_hi, g_xt_hi);
    cudaGetSymbolAddress((void**)&xt_lo, g_xt_lo);
    cudaGetSymbolAddress((void**)&at_hi, g_at_hi);
    cudaGetSymbolAddress((void**)&at_lo, g_at_lo);
    cudaGetSymbolAddress((void**)&wq_hi, g_wq_hi);
    cudaGetSymbolAddress((void**)&wq_lo, g_wq_lo);
    cudaGetSymbolAddress((void**)&wp_hi, g_wp_hi);
    cudaGetSymbolAddress((void**)&wp_lo, g_wp_lo);

    cudaFuncSetAttribute(win_attn_kernel, cudaFuncAttributeMaxDynamicSharedMemorySize, SMEM_BYTES);
    cudaFuncSetAttribute(hmma_gemm<0>, cudaFuncAttributeMaxDynamicSharedMemorySize, HG_SMEM);
    cudaFuncSetAttribute(hmma_gemm<1>, cudaFuncAttributeMaxDynamicSharedMemorySize, HG_SMEM);

    // weight splits
    split_w<<<(QKV_M * DIMC + 255) / 256, 256>>>(qkv_w, wq_hi, wq_lo, QKV_M * DIMC);
    split_w<<<(DIMC * DIMC + 255) / 256, 256>>>(proj_w, wp_hi, wp_lo, DIMC * DIMC);

    // x -> transposed hi/lo bf16 [b][hw][384]
    transpose_split<<<dim3(HW / 32, DIMC / 32, BATCH), 256>>>(x, xt_hi, xt_lo, DIMC, HW);

    // qkv = W_qkv . x   -> g_qkv [b][1152][hw] f32
    hmma_gemm<0><<<dim3(QKV_M / 128, HW / 128, BATCH), 256, HG_SMEM>>>(
        wq_hi, wq_lo, xt_hi, xt_lo, qkv_buf, QKV_M, HW, DIMC, nullptr);

    // fused dwconv + window channel attention -> bf16 hi/lo [b][hw][384]
    win_attn_kernel<<<dim3(1024, HEADS, BATCH), 256, SMEM_BYTES>>>(
        qkv_buf, dw_w, temp, at_hi, at_lo);

    // out = W_proj . att + b
    hmma_gemm<1><<<dim3(DIMC / 128, HW / 128, BATCH), 256, HG_SMEM>>>(
        wp_hi, wp_lo, at_hi, at_lo, out, DIMC, HW, DIMC, proj_b);
}

// round 6
// speedup vs baseline: 2.2280x; 1.0675x over previous
#include <cuda_runtime.h>
#include <cuda_bf16.h>
#include <cstdint>
#include <math.h>

// Problem constants
#define DIMC   384
#define HEADS  8
#define CPH    48
#define HH     256
#define WW     256
#define HW     65536
#define BATCH  2
#define QKV_M  1152        // 3*dim

// ---------------- scratch (device globals) ----------------------------------
__device__ float g_qkv[(size_t)BATCH * QKV_M * HW];           // [b][1152][hw] f32
__device__ __nv_bfloat16 g_xt_hi[(size_t)BATCH * HW * DIMC];  // [b][hw][384]
__device__ __nv_bfloat16 g_xt_lo[(size_t)BATCH * HW * DIMC];
__device__ __nv_bfloat16 g_at_hi[(size_t)BATCH * HW * DIMC];
__device__ __nv_bfloat16 g_at_lo[(size_t)BATCH * HW * DIMC];
__device__ __nv_bfloat16 g_wq_hi[QKV_M * DIMC], g_wq_lo[QKV_M * DIMC];
__device__ __nv_bfloat16 g_wp_hi[DIMC * DIMC],  g_wp_lo[DIMC * DIMC];

// ---------------- helpers ----------------------------------------------------
__device__ __forceinline__ uint32_t smem_u32(const void* p) {
    uint32_t a;
    asm("{ .reg .u64 t; cvta.to.shared.u64 t, %1; cvt.u32.u64 %0, t; }" : "=r"(a) : "l"(p));
    return a;
}
#define CP_ASYNC16(saddr, gptr) \
    asm volatile("cp.async.cg.shared.global [%0], [%1], 16;" :: "r"(saddr), "l"(gptr))
#define CP_COMMIT() asm volatile("cp.async.commit_group;" ::: "memory")
#define CP_WAIT2()  asm volatile("cp.async.wait_group 2;" ::: "memory")

__device__ __forceinline__ void ldmx4(uint32_t* d, uint32_t addr) {
    asm volatile("ldmatrix.sync.aligned.m8n8.x4.shared.b16 {%0,%1,%2,%3}, [%4];"
                 : "=r"(d[0]), "=r"(d[1]), "=r"(d[2]), "=r"(d[3]) : "r"(addr));
}
__device__ __forceinline__ void mma16816(float* c, const uint32_t* a, uint32_t b0, uint32_t b1) {
    asm volatile("mma.sync.aligned.m16n8k16.row.col.f32.bf16.bf16.f32 "
                 "{%0,%1,%2,%3}, {%4,%5,%6,%7}, {%8,%9}, {%0,%1,%2,%3};"
                 : "+f"(c[0]), "+f"(c[1]), "+f"(c[2]), "+f"(c[3])
                 : "r"(a[0]), "r"(a[1]), "r"(a[2]), "r"(a[3]), "r"(b0), "r"(b1));
}
__device__ __forceinline__ uint32_t swz(int r, int cb) {
    return (uint32_t)(r * 64 + ((cb ^ ((r >> 1) & 3)) << 4));
}

// ---------------- transpose + hi/lo bf16 split (for x only) ------------------
__global__ __launch_bounds__(256) void transpose_split(
    const float* __restrict__ in, __nv_bfloat16* __restrict__ hi,
    __nv_bfloat16* __restrict__ lo, int C, int N)
{
    __shared__ float t[32][33];
    const int n0 = blockIdx.x * 32, c0 = blockIdx.y * 32;
    const size_t base = (size_t)blockIdx.z * C * N;
    const int tx = threadIdx.x & 31, ty = threadIdx.x >> 5;
#pragma unroll
    for (int i = 0; i < 4; i++) {
        const int c = ty + i * 8;
        t[c][tx] = in[base + (size_t)(c0 + c) * N + n0 + tx];
    }
    __syncthreads();
#pragma unroll
    for (int i = 0; i < 4; i++) {
        const int n = ty + i * 8;
        const float v = t[tx][n];
        const __nv_bfloat16 h = __float2bfloat16(v);
        const size_t o = base + (size_t)(n0 + n) * C + c0 + tx;
        hi[o] = h;
        lo[o] = __float2bfloat16(v - __bfloat162float(h));
    }
}

__global__ void split_w(const float* __restrict__ w, __nv_bfloat16* __restrict__ hi,
                        __nv_bfloat16* __restrict__ lo, int n)
{
    const int i = blockIdx.x * 256 + threadIdx.x;
    if (i < n) {
        const float v = w[i];
        const __nv_bfloat16 h = __float2bfloat16(v);
        hi[i] = h;
        lo[i] = __float2bfloat16(v - __bfloat162float(h));
    }
}

// ---------------- HMMA GEMM: C[M,N] = A[M,K] . B[N,K]^T ---------------------
#define HG_SMEM 98304

template <int WITH_BIAS>
__global__ __launch_bounds__(256) void hmma_gemm(
    const __nv_bfloat16* __restrict__ Ahi, const __nv_bfloat16* __restrict__ Alo,
    const __nv_bfloat16* __restrict__ Bhi, const __nv_bfloat16* __restrict__ Blo,
    float* __restrict__ Cg, int M, int N, int K, const float* __restrict__ bias)
{
    extern __shared__ char smem[];
    const uint32_t sb = smem_u32(smem);
    const int tid = threadIdx.x;
    const int wid = tid >> 5, lane = tid & 31;
    const int bM = blockIdx.x * 128;
    const int bN = blockIdx.y * 128;
    const size_t bb = (size_t)blockIdx.z * (size_t)N * K;
    float* Cp = Cg + (size_t)blockIdx.z * (size_t)M * N;

    const __nv_bfloat16* Ah = Ahi + (size_t)bM * K;
    const __nv_bfloat16* Al = Alo + (size_t)bM * K;
    const __nv_bfloat16* Bh = Bhi + bb + (size_t)bN * K;
    const __nv_bfloat16* Bl = Blo + bb + (size_t)bN * K;

    const int cb = tid & 3;
    const int r0 = tid >> 2;
    const int nst = K / 32;

#pragma unroll
    for (int ps = 0; ps < 2; ps++) {
        const uint32_t st = sb + ps * 32768;
        const int kk = ps * 32 + cb * 8;
#pragma unroll
        for (int i = 0; i < 2; i++) {
            const int r = r0 + i * 64;
            const uint32_t so = swz(r, cb);
            CP_ASYNC16(st + so,         Ah + (size_t)r * K + kk);
            CP_ASYNC16(st + 8192 + so,  Al + (size_t)r * K + kk);
            CP_ASYNC16(st + 16384 + so, Bh + (size_t)r * K + kk);
            CP_ASYNC16(st + 24576 + so, Bl + (size_t)r * K + kk);
        }
        CP_COMMIT();
    }

    float acc[4][4][4];
#pragma unroll
    for (int i = 0; i < 4; i++)
#pragma unroll
        for (int j = 0; j < 4; j++)
#pragma unroll
            for (int k = 0; k < 4; k++) acc[i][j][k] = 0.f;

    const int wm = (wid >> 2) * 64;
    const int wn = (wid & 3) * 32;
    const int a_rbase = wm + ((lane >> 3) & 1) * 8 + (lane & 7);
    const int a_cbad  = lane >> 4;
    const int b_rbase = wn + ((lane >> 4) & 1) * 8 + (lane & 7);
    const int b_cbad  = (lane >> 3) & 1;

    int sidx = 0;
    for (int s = 0; s < nst; s++) {
        if (s + 2 < nst) {
            int fi = sidx + 2; if (fi >= 3) fi -= 3;
            const uint32_t st = sb + fi * 32768;
            const int kk = (s + 2) * 32 + cb * 8;
#pragma unroll
            for (int i = 0; i < 2; i++) {
                const int r = r0 + i * 64;
                const uint32_t so = swz(r, cb);
                CP_ASYNC16(st + so,         Ah + (size_t)r * K + kk);
                CP_ASYNC16(st + 8192 + so,  Al + (size_t)r * K + kk);
                CP_ASYNC16(st + 16384 + so, Bh + (size_t)r * K + kk);
                CP_ASYNC16(st + 24576 + so, Bl + (size_t)r * K + kk);
            }
        }
        CP_COMMIT();
        CP_WAIT2();
        __syncthreads();

        const uint32_t st = sb + sidx * 32768;
#pragma unroll
        for (int k16 = 0; k16 < 2; k16++) {
            uint32_t bhf[2][4], blf[2][4];
#pragma unroll
            for (int nh = 0; nh < 2; nh++) {
                const uint32_t ad = st + 16384 + swz(b_rbase + nh * 16, k16 * 2 + b_cbad);
                ldmx4(bhf[nh], ad);
                ldmx4(blf[nh], ad + 8192);
            }
#pragma unroll
            for (int mh = 0; mh < 4; mh++) {
                uint32_t ahf[4], alf[4];
                const uint32_t ad = st + swz(a_rbase + mh * 16, k16 * 2 + a_cbad);
                ldmx4(ahf, ad);
                ldmx4(alf, ad + 8192);
#pragma unroll
                for (int nb = 0; nb < 4; nb++) {
                    const uint32_t* fh = &bhf[nb >> 1][(nb & 1) * 2];
                    const uint32_t* fl = &blf[nb >> 1][(nb & 1) * 2];
                    mma16816(acc[mh][nb], ahf, fh[0], fh[1]);
                    mma16816(acc[mh][nb], ahf, fl[0], fl[1]);
                    mma16816(acc[mh][nb], alf, fh[0], fh[1]);
                }
            }
        }
        __syncthreads();
        if (++sidx == 3) sidx = 0;
    }

    const int row0 = bM + wm + (lane >> 2);
    const int col0 = bN + wn + (lane & 3) * 2;
#pragma unroll
    for (int mh = 0; mh < 4; mh++) {
#pragma unroll
        for (int p = 0; p < 2; p++) {
            const int row = row0 + mh * 16 + p * 8;
            const float bi = WITH_BIAS ? __ldg(&bias[row]) : 0.f;
#pragma unroll
            for (int nb = 0; nb < 4; nb++) {
                float2 v;
                v.x = acc[mh][nb][p * 2 + 0] + bi;
                v.y = acc[mh][nb][p * 2 + 1] + bi;
                *reinterpret_cast<float2*>(&Cp[(size_t)row * N + col0 + nb * 8]) = v;
            }
        }
    }
}

// ---------------- Fused dwconv 3x3 + window channel-attention ---------------
// One block per (window, head). 256 threads.
#define SQ 68                                   // s_qkv row stride (16B-aligned)
#define S_HALO_STRIDE 100
#define S_ATTN_STRIDE 49
#define OFF_HALO 0                              // 48*100  = 4800 floats
#define OFF_QKV  4800                           // 144*68  = 9792
#define OFF_ATTN (4800 + 9792)                  // 48*49   = 2352
#define OFF_DWW  (OFF_ATTN + 2352)              // 144*9   = 1296
#define SMEM_FLOATS (OFF_DWW + 1296)            // 18240
#define SMEM_BYTES  (SMEM_FLOATS * 4)           // 72960

__global__ __launch_bounds__(256) void win_attn_kernel(
    const float* __restrict__ qkv1,          // [b][1152][hw] f32
    const float* __restrict__ dww,           // [1152][9]
    const float* __restrict__ temperature,   // [8]
    __nv_bfloat16* __restrict__ out_hi,      // [b][hw][384]
    __nv_bfloat16* __restrict__ out_lo)
{
    extern __shared__ float sm[];
    float* s_halo = sm + OFF_HALO;           // 48 x 100 (reused as out 48 x SQ)
    float* s_qkv  = sm + OFF_QKV;            // 144 x SQ
    float* s_attn = sm + OFF_ATTN;           // 48 x 49
    float* s_dww  = sm + OFF_DWW;            // 144 x 9

    const int tid  = threadIdx.x;
    const int wblk = blockIdx.x;
    const int head = blockIdx.y;
    const int b    = blockIdx.z;
    const int wy = wblk >> 5, wx = wblk & 31;
    const int y0 = wy * 8 - 1, x0 = wx * 8 - 1;
    const size_t chan_base = ((size_t)b * QKV_M) * HW;
    const bool interior = (wy > 0) && (wy < 31) && (wx > 0) && (wx < 31);

    // depthwise weights for all 3 z-groups of this head
    for (int e = tid; e < 144 * 9; e += 256) {
        const int l = e / 9, kk = e - l * 9;
        const int z = l / 48, cl = l - z * 48;
        s_dww[e] = dww[(size_t)(z * DIMC + head * CPH + cl) * 9 + kk];
    }

    // ---------- halo loader (48 ch x 10x10) ----------
    auto load_halo = [&](int z) {
        const float* src = qkv1 + chan_base + (size_t)(z * DIMC + head * CPH) * HW;
        if (interior) {
            for (int e = tid; e < 4800; e += 256) {
                const int l = e / 100, p = e - l * 100;
                const int ly = p / 10, lx = p - ly * 10;
                s_halo[e] = src[(size_t)l * HW + ((y0 + ly) << 8) + (x0 + lx)];
            }
        } else {
            for (int e = tid; e < 4800; e += 256) {
                const int l = e / 100, p = e - l * 100;
                const int ly = p / 10, lx = p - ly * 10;
                const int y = y0 + ly, x = x0 + lx;
                float v = 0.f;
                if ((unsigned)y < (unsigned)HH && (unsigned)x < (unsigned)WW)
                    v = src[(size_t)l * HW + (y << 8) + x];
                s_halo[e] = v;
            }
        }
    };

    // ---------- sliding-window dwconv for one z-group ----------
    auto dwconv = [&](int z) {
#pragma unroll 1
        for (int u = tid; u < 384; u += 256) {
            const int ch = u >> 3;         // 0..47
            const int row = u & 7;         // 0..7
            const float* hb = s_halo + ch * S_HALO_STRIDE + row * 10;
            const float* wb = s_dww + (z * 48 + ch) * 9;
            float w[9];
#pragma unroll
            for (int i = 0; i < 9; i++) w[i] = wb[i];
            float h[3][10];
#pragma unroll
            for (int dy = 0; dy < 3; dy++)
#pragma unroll
                for (int c = 0; c < 10; c++) h[dy][c] = hb[dy * 10 + c];
            float o[8];
#pragma unroll
            for (int x = 0; x < 8; x++) {
                o[x] = h[0][x] * w[0] + h[0][x + 1] * w[1] + h[0][x + 2] * w[2]
                     + h[1][x] * w[3] + h[1][x + 1] * w[4] + h[1][x + 2] * w[5]
                     + h[2][x] * w[6] + h[2][x + 1] * w[7] + h[2][x + 2] * w[8];
            }
            float* dst = s_qkv + (z * 48 + ch) * SQ + row * 8;
            *reinterpret_cast<float4*>(dst)     = make_float4(o[0], o[1], o[2], o[3]);
            *reinterpret_cast<float4*>(dst + 4) = make_float4(o[4], o[5], o[6], o[7]);
        }
    };

    // ---- q, k: halo + dwconv ----
    load_halo(0);
    __syncthreads();                  // also covers s_dww
    dwconv(0);
    __syncthreads();
    load_halo(1);
    __syncthreads();
    dwconv(1);
    __syncthreads();

    // ---- v halo load (latency hidden behind norm/QK) ----
    load_halo(2);

    // ---- L2 normalize q,k (96 rows of 64); 8 lanes per row ----
    {
        const int grp = tid >> 3;      // 0..31
        const int gl  = tid & 7;
#pragma unroll
        for (int it = 0; it < 3; it++) {
            const int r = grp + it * 32;
            float* rp = s_qkv + r * SQ + gl * 8;
            float4 v0 = *reinterpret_cast<float4*>(rp);
            float4 v1 = *reinterpret_cast<float4*>(rp + 4);
            float s = v0.x * v0.x + v0.y * v0.y + v0.z * v0.z + v0.w * v0.w
                    + v1.x * v1.x + v1.y * v1.y + v1.z * v1.z + v1.w * v1.w;
            s += __shfl_xor_sync(0xffffffffu, s, 1);
            s += __shfl_xor_sync(0xffffffffu, s, 2);
            s += __shfl_xor_sync(0xffffffffu, s, 4);
            const float inv = 1.f / fmaxf(sqrtf(s), 1e-12f);
            v0.x *= inv; v0.y *= inv; v0.z *= inv; v0.w *= inv;
            v1.x *= inv; v1.y *= inv; v1.z *= inv; v1.w *= inv;
            *reinterpret_cast<float4*>(rp)     = v0;
            *reinterpret_cast<float4*>(rp + 4) = v1;
        }
    }
    __syncthreads();                  // norm writes + v halo complete

    const float temp = __ldg(&temperature[head]);

    // ---- attn[c][d] = (q_c . k_d) * temp  (48x48, K=64), float4 over n ----
    {
        const int ty = tid >> 4, tx = tid & 15;
        float acc[3][3];
#pragma unroll
        for (int i = 0; i < 3; i++)
#pragma unroll
            for (int j = 0; j < 3; j++) acc[i][j] = 0.f;
        const float* qb = s_qkv + (ty * 3) * SQ;
        const float* kb = s_qkv + (48 + tx * 3) * SQ;
#pragma unroll 4
        for (int n = 0; n < 64; n += 4) {
            const float4 q0 = *reinterpret_cast<const float4*>(qb + n);
            const float4 q1 = *reinterpret_cast<const float4*>(qb + SQ + n);
            const float4 q2 = *reinterpret_cast<const float4*>(qb + 2 * SQ + n);
            const float4 k0 = *reinterpret_cast<const float4*>(kb + n);
            const float4 k1 = *reinterpret_cast<const float4*>(kb + SQ + n);
            const float4 k2 = *reinterpret_cast<const float4*>(kb + 2 * SQ + n);
            acc[0][0] += q0.x*k0.x + q0.y*k0.y + q0.z*k0.z + q0.w*k0.w;
            acc[0][1] += q0.x*k1.x + q0.y*k1.y + q0.z*k1.z + q0.w*k1.w;
            acc[0][2] += q0.x*k2.x + q0.y*k2.y + q0.z*k2.z + q0.w*k2.w;
            acc[1][0] += q1.x*k0.x + q1.y*k0.y + q1.z*k0.z + q1.w*k0.w;
            acc[1][1] += q1.x*k1.x + q1.y*k1.y + q1.z*k1.z + q1.w*k1.w;
            acc[1][2] += q1.x*k2.x + q1.y*k2.y + q1.z*k2.z + q1.w*k2.w;
            acc[2][0] += q2.x*k0.x + q2.y*k0.y + q2.z*k0.z + q2.w*k0.w;
            acc[2][1] += q2.x*k1.x + q2.y*k1.y + q2.z*k1.z + q2.w*k1.w;
            acc[2][2] += q2.x*k2.x + q2.y*k2.y + q2.z*k2.z + q2.w*k2.w;
        }
#pragma unroll
        for (int i = 0; i < 3; i++)
#pragma unroll
            for (int j = 0; j < 3; j++)
                s_attn[(ty * 3 + i) * S_ATTN_STRIDE + tx * 3 + j] = acc[i][j] * temp;
    }
    __syncthreads();

    // ---- softmax over d ----
    {
        const int warp = tid >> 5, lane = tid & 31;
        for (int r = warp; r < 48; r += 8) {
            const float v0 = s_attn[r * S_ATTN_STRIDE + lane];
            const float v1 = (lane < 16) ? s_attn[r * S_ATTN_STRIDE + lane + 32] : -1e30f;
            float m = fmaxf(v0, v1);
#pragma unroll
            for (int off = 16; off; off >>= 1) m = fmaxf(m, __shfl_xor_sync(0xffffffffu, m, off));
            const float e0 = __expf(v0 - m);
            const float e1 = (lane < 16) ? __expf(v1 - m) : 0.f;
            float s = e0 + e1;
#pragma unroll
            for (int off = 16; off; off >>= 1) s += __shfl_xor_sync(0xffffffffu, s, off);
            const float inv = 1.f / s;
            s_attn[r * S_ATTN_STRIDE + lane] = e0 * inv;
            if (lane < 16) s_attn[r * S_ATTN_STRIDE + lane + 32] = e1 * inv;
        }
    }

    // ---- dwconv v (z=2): s_halo -> s_qkv rows 96..143 ----
    dwconv(2);
    __syncthreads();

    // ---- out[c][n] = sum_d attn[c][d] * v[d][n] -> s_out (reuse s_halo) ----
    float* s_out = s_halo;   // 48 x SQ (3264 <= 4800)
    {
        const int ty = tid >> 4, tx = tid & 15;
        float4 a0c = make_float4(0.f, 0.f, 0.f, 0.f);
        float4 a1c = a0c, a2c = a0c;
        const float* ar0 = s_attn + (ty * 3 + 0) * S_ATTN_STRIDE;
        const float* ar1 = s_attn + (ty * 3 + 1) * S_ATTN_STRIDE;
        const float* ar2 = s_attn + (ty * 3 + 2) * S_ATTN_STRIDE;
#pragma unroll 4
        for (int d = 0; d < 48; ++d) {
            const float a0 = ar0[d], a1 = ar1[d], a2 = ar2[d];
            const float4 v = *reinterpret_cast<const float4*>(&s_qkv[(96 + d) * SQ + tx * 4]);
            a0c.x += a0 * v.x; a0c.y += a0 * v.y; a0c.z += a0 * v.z; a0c.w += a0 * v.w;
            a1c.x += a1 * v.x; a1c.y += a1 * v.y; a1c.z += a1 * v.z; a1c.w += a1 * v.w;
            a2c.x += a2 * v.x; a2c.y += a2 * v.y; a2c.z += a2 * v.z; a2c.w += a2 * v.w;
        }
        *reinterpret_cast<float4*>(&s_out[(ty * 3 + 0) * SQ + tx * 4]) = a0c;
        *reinterpret_cast<float4*>(&s_out[(ty * 3 + 1) * SQ + tx * 4]) = a1c;
        *reinterpret_cast<float4*>(&s_out[(ty * 3 + 2) * SQ + tx * 4]) = a2c;
    }
    __syncthreads();

    // ---- write bf16 hi/lo to [b][hw][384] (fused transpose + split) --------
    for (int e = tid; e < 1536; e += 256) {
        const int c2 = e % 24;           // pair index -> c = 2*c2
        const int n  = e / 24;
        const int c  = c2 * 2;
        const float va = s_out[c * SQ + n];
        const float vb = s_out[(c + 1) * SQ + n];
        const int yy = n >> 3, xx = n & 7;
        const int hw = ((wy * 8 + yy) << 8) + wx * 8 + xx;
        const size_t off = ((size_t)b * HW + hw) * DIMC + head * CPH + c;
        const __nv_bfloat16 ha = __float2bfloat16(va);
        const __nv_bfloat16 hb = __float2bfloat16(vb);
        __nv_bfloat162 hi2, lo2;
        hi2.x = ha; hi2.y = hb;
        lo2.x = __float2bfloat16(va - __bfloat162float(ha));
        lo2.y = __float2bfloat16(vb - __bfloat162float(hb));
        *reinterpret_cast<__nv_bfloat162*>(&out_hi[off]) = hi2;
        *reinterpret_cast<__nv_bfloat162*>(&out_lo[off]) = lo2;
    }
}

// ---------------- launch ----------------------------------------------------
extern "C" void kernel_launch(void* const* d_in, const int* in_sizes, int n_in,
                              void* d_out, int out_size)
{
    const float* x      = (const float*)d_in[0];
    const float* qkv_w  = (const float*)d_in[1];
    const float* dw_w   = (const float*)d_in[2];
    const float* temp   = (const float*)d_in[3];
    const float* proj_w = (const float*)d_in[4];
    const float* proj_b = (const float*)d_in[5];
    float* out = (float*)d_out;

    float *qkv_buf;
    __nv_bfloat16 *xt_hi, *xt_lo, *at_hi, *at_lo, *wq_hi, *wq_lo, *wp_hi, *wp_lo;
    cudaGetSymbolAddress((void**)&qkv_buf, g_qkv);
    cudaGetSymbolAddress((void**)&xt_hi, g_xt_hi);
    cudaGetSymbolAddress((void**)&xt_lo, g_xt_lo);
    cudaGetSymbolAddress((void**)&at_hi, g_at_hi);
    cudaGetSymbolAddress((void**)&at_lo, g_at_lo);
    cudaGetSymbolAddress((void**)&wq_hi, g_wq_hi);
    cudaGetSymbolAddress((void**)&wq_lo, g_wq_lo);
    cudaGetSymbolAddress((void**)&wp_hi, g_wp_hi);
    cudaGetSymbolAddress((void**)&wp_lo, g_wp_lo);

    cudaFuncSetAttribute(win_attn_kernel, cudaFuncAttributeMaxDynamicSharedMemorySize, SMEM_BYTES);
    cudaFuncSetAttribute(hmma_gemm<0>, cudaFuncAttributeMaxDynamicSharedMemorySize, HG_SMEM);
    cudaFuncSetAttribute(hmma_gemm<1>, cudaFuncAttributeMaxDynamicSharedMemorySize, HG_SMEM);

    // weight splits
    split_w<<<(QKV_M * DIMC + 255) / 256, 256>>>(qkv_w, wq_hi, wq_lo, QKV_M * DIMC);
    split_w<<<(DIMC * DIMC + 255) / 256, 256>>>(proj_w, wp_hi, wp_lo, DIMC * DIMC);

    // x -> transposed hi/lo bf16 [b][hw][384]
    transpose_split<<<dim3(HW / 32, DIMC / 32, BATCH), 256>>>(x, xt_hi, xt_lo, DIMC, HW);

    // qkv = W_qkv . x   -> g_qkv [b][1152][hw] f32
    hmma_gemm<0><<<dim3(QKV_M / 128, HW / 128, BATCH), 256, HG_SMEM>>>(
        wq_hi, wq_lo, xt_hi, xt_lo, qkv_buf, QKV_M, HW, DIMC, nullptr);

    // fused dwconv + window channel attention -> bf16 hi/lo [b][hw][384]
    win_attn_kernel<<<dim3(1024, HEADS, BATCH), 256, SMEM_BYTES>>>(
        qkv_buf, dw_w, temp, at_hi, at_lo);

    // out = W_proj . att + b
    hmma_gemm<1><<<dim3(DIMC / 128, HW / 128, BATCH), 256, HG_SMEM>>>(
        wp_hi, wp_lo, at_hi, at_lo, out, DIMC, HW, DIMC, proj_b);
}

// round 7
// speedup vs baseline: 2.6500x; 1.1894x over previous
#include <cuda_runtime.h>
#include <cuda_bf16.h>
#include <cstdint>
#include <math.h>

// Problem constants
#define DIMC   384
#define HEADS  8
#define CPH    48
#define HH     256
#define WW     256
#define HW     65536
#define BATCH  2
#define QKV_M  1152        // 3*dim

// ---------------- scratch (device globals) ----------------------------------
__device__ float g_qkv[(size_t)BATCH * QKV_M * HW];           // [b][1152][hw] f32
__device__ float g_win[(size_t)BATCH * HEADS * 1024 * 144 * 64]; // window-major dwconv out
__device__ __nv_bfloat16 g_xt_hi[(size_t)BATCH * HW * DIMC];  // [b][hw][384]
__device__ __nv_bfloat16 g_xt_lo[(size_t)BATCH * HW * DIMC];
__device__ __nv_bfloat16 g_at_hi[(size_t)BATCH * HW * DIMC];
__device__ __nv_bfloat16 g_at_lo[(size_t)BATCH * HW * DIMC];
__device__ __nv_bfloat16 g_wq_hi[QKV_M * DIMC], g_wq_lo[QKV_M * DIMC];
__device__ __nv_bfloat16 g_wp_hi[DIMC * DIMC],  g_wp_lo[DIMC * DIMC];

// ---------------- helpers ----------------------------------------------------
__device__ __forceinline__ uint32_t smem_u32(const void* p) {
    uint32_t a;
    asm("{ .reg .u64 t; cvta.to.shared.u64 t, %1; cvt.u32.u64 %0, t; }" : "=r"(a) : "l"(p));
    return a;
}
#define CP_ASYNC16(saddr, gptr) \
    asm volatile("cp.async.cg.shared.global [%0], [%1], 16;" :: "r"(saddr), "l"(gptr))
#define CP_COMMIT() asm volatile("cp.async.commit_group;" ::: "memory")
#define CP_WAIT0()  asm volatile("cp.async.wait_group 0;" ::: "memory")
#define CP_WAIT1()  asm volatile("cp.async.wait_group 1;" ::: "memory")
#define CP_WAIT2()  asm volatile("cp.async.wait_group 2;" ::: "memory")

__device__ __forceinline__ void ldmx4(uint32_t* d, uint32_t addr) {
    asm volatile("ldmatrix.sync.aligned.m8n8.x4.shared.b16 {%0,%1,%2,%3}, [%4];"
                 : "=r"(d[0]), "=r"(d[1]), "=r"(d[2]), "=r"(d[3]) : "r"(addr));
}
__device__ __forceinline__ void mma16816(float* c, const uint32_t* a, uint32_t b0, uint32_t b1) {
    asm volatile("mma.sync.aligned.m16n8k16.row.col.f32.bf16.bf16.f32 "
                 "{%0,%1,%2,%3}, {%4,%5,%6,%7}, {%8,%9}, {%0,%1,%2,%3};"
                 : "+f"(c[0]), "+f"(c[1]), "+f"(c[2]), "+f"(c[3])
                 : "r"(a[0]), "r"(a[1]), "r"(a[2]), "r"(a[3]), "r"(b0), "r"(b1));
}
__device__ __forceinline__ uint32_t swz(int r, int cb) {
    return (uint32_t)(r * 64 + ((cb ^ ((r >> 1) & 3)) << 4));
}

// ---------------- transpose + hi/lo bf16 split (for x only) ------------------
__global__ __launch_bounds__(256) void transpose_split(
    const float* __restrict__ in, __nv_bfloat16* __restrict__ hi,
    __nv_bfloat16* __restrict__ lo, int C, int N)
{
    __shared__ float t[32][33];
    const int n0 = blockIdx.x * 32, c0 = blockIdx.y * 32;
    const size_t base = (size_t)blockIdx.z * C * N;
    const int tx = threadIdx.x & 31, ty = threadIdx.x >> 5;
#pragma unroll
    for (int i = 0; i < 4; i++) {
        const int c = ty + i * 8;
        t[c][tx] = in[base + (size_t)(c0 + c) * N + n0 + tx];
    }
    __syncthreads();
#pragma unroll
    for (int i = 0; i < 4; i++) {
        const int n = ty + i * 8;
        const float v = t[tx][n];
        const __nv_bfloat16 h = __float2bfloat16(v);
        const size_t o = base + (size_t)(n0 + n) * C + c0 + tx;
        hi[o] = h;
        lo[o] = __float2bfloat16(v - __bfloat162float(h));
    }
}

__global__ void split_w(const float* __restrict__ w, __nv_bfloat16* __restrict__ hi,
                        __nv_bfloat16* __restrict__ lo, int n)
{
    const int i = blockIdx.x * 256 + threadIdx.x;
    if (i < n) {
        const float v = w[i];
        const __nv_bfloat16 h = __float2bfloat16(v);
        hi[i] = h;
        lo[i] = __float2bfloat16(v - __bfloat162float(h));
    }
}

// ---------------- HMMA GEMM: C[M,N] = A[M,K] . B[N,K]^T ---------------------
#define HG_SMEM 98304

template <int WITH_BIAS>
__global__ __launch_bounds__(256) void hmma_gemm(
    const __nv_bfloat16* __restrict__ Ahi, const __nv_bfloat16* __restrict__ Alo,
    const __nv_bfloat16* __restrict__ Bhi, const __nv_bfloat16* __restrict__ Blo,
    float* __restrict__ Cg, int M, int N, int K, const float* __restrict__ bias)
{
    extern __shared__ char smem[];
    const uint32_t sb = smem_u32(smem);
    const int tid = threadIdx.x;
    const int wid = tid >> 5, lane = tid & 31;
    const int bM = blockIdx.x * 128;
    const int bN = blockIdx.y * 128;
    const size_t bb = (size_t)blockIdx.z * (size_t)N * K;
    float* Cp = Cg + (size_t)blockIdx.z * (size_t)M * N;

    const __nv_bfloat16* Ah = Ahi + (size_t)bM * K;
    const __nv_bfloat16* Al = Alo + (size_t)bM * K;
    const __nv_bfloat16* Bh = Bhi + bb + (size_t)bN * K;
    const __nv_bfloat16* Bl = Blo + bb + (size_t)bN * K;

    const int cb = tid & 3;
    const int r0 = tid >> 2;
    const int nst = K / 32;

#pragma unroll
    for (int ps = 0; ps < 2; ps++) {
        const uint32_t st = sb + ps * 32768;
        const int kk = ps * 32 + cb * 8;
#pragma unroll
        for (int i = 0; i < 2; i++) {
            const int r = r0 + i * 64;
            const uint32_t so = swz(r, cb);
            CP_ASYNC16(st + so,         Ah + (size_t)r * K + kk);
            CP_ASYNC16(st + 8192 + so,  Al + (size_t)r * K + kk);
            CP_ASYNC16(st + 16384 + so, Bh + (size_t)r * K + kk);
            CP_ASYNC16(st + 24576 + so, Bl + (size_t)r * K + kk);
        }
        CP_COMMIT();
    }

    float acc[4][4][4];
#pragma unroll
    for (int i = 0; i < 4; i++)
#pragma unroll
        for (int j = 0; j < 4; j++)
#pragma unroll
            for (int k = 0; k < 4; k++) acc[i][j][k] = 0.f;

    const int wm = (wid >> 2) * 64;
    const int wn = (wid & 3) * 32;
    const int a_rbase = wm + ((lane >> 3) & 1) * 8 + (lane & 7);
    const int a_cbad  = lane >> 4;
    const int b_rbase = wn + ((lane >> 4) & 1) * 8 + (lane & 7);
    const int b_cbad  = (lane >> 3) & 1;

    int sidx = 0;
    for (int s = 0; s < nst; s++) {
        if (s + 2 < nst) {
            int fi = sidx + 2; if (fi >= 3) fi -= 3;
            const uint32_t st = sb + fi * 32768;
            const int kk = (s + 2) * 32 + cb * 8;
#pragma unroll
            for (int i = 0; i < 2; i++) {
                const int r = r0 + i * 64;
                const uint32_t so = swz(r, cb);
                CP_ASYNC16(st + so,         Ah + (size_t)r * K + kk);
                CP_ASYNC16(st + 8192 + so,  Al + (size_t)r * K + kk);
                CP_ASYNC16(st + 16384 + so, Bh + (size_t)r * K + kk);
                CP_ASYNC16(st + 24576 + so, Bl + (size_t)r * K + kk);
            }
        }
        CP_COMMIT();
        CP_WAIT2();
        __syncthreads();

        const uint32_t st = sb + sidx * 32768;
#pragma unroll
        for (int k16 = 0; k16 < 2; k16++) {
            uint32_t bhf[2][4], blf[2][4];
#pragma unroll
            for (int nh = 0; nh < 2; nh++) {
                const uint32_t ad = st + 16384 + swz(b_rbase + nh * 16, k16 * 2 + b_cbad);
                ldmx4(bhf[nh], ad);
                ldmx4(blf[nh], ad + 8192);
            }
#pragma unroll
            for (int mh = 0; mh < 4; mh++) {
                uint32_t ahf[4], alf[4];
                const uint32_t ad = st + swz(a_rbase + mh * 16, k16 * 2 + a_cbad);
                ldmx4(ahf, ad);
                ldmx4(alf, ad + 8192);
#pragma unroll
                for (int nb = 0; nb < 4; nb++) {
                    const uint32_t* fh = &bhf[nb >> 1][(nb & 1) * 2];
                    const uint32_t* fl = &blf[nb >> 1][(nb & 1) * 2];
                    mma16816(acc[mh][nb], ahf, fh[0], fh[1]);
                    mma16816(acc[mh][nb], ahf, fl[0], fl[1]);
                    mma16816(acc[mh][nb], alf, fh[0], fh[1]);
                }
            }
        }
        __syncthreads();
        if (++sidx == 3) sidx = 0;
    }

    const int row0 = bM + wm + (lane >> 2);
    const int col0 = bN + wn + (lane & 3) * 2;
#pragma unroll
    for (int mh = 0; mh < 4; mh++) {
#pragma unroll
        for (int p = 0; p < 2; p++) {
            const int row = row0 + mh * 16 + p * 8;
            const float bi = WITH_BIAS ? __ldg(&bias[row]) : 0.f;
#pragma unroll
            for (int nb = 0; nb < 4; nb++) {
                float2 v;
                v.x = acc[mh][nb][p * 2 + 0] + bi;
                v.y = acc[mh][nb][p * 2 + 1] + bi;
                *reinterpret_cast<float2*>(&Cp[(size_t)row * N + col0 + nb * 8]) = v;
            }
        }
    }
}

// ---------------- dwconv 3x3 -> window-major layout --------------------------
// grid (64 tiles of 32x32, 8 heads, 2 batch); 256 threads.
// Streams 144 channels with double-buffered cp.async halo (34 rows x 40 cols).
// Output: g_win[(b*8+head)*1024 + win][144][64] f32.
#define HSTR 40

__global__ __launch_bounds__(256) void dwconv_kernel(
    const float* __restrict__ qkv1,     // [b][1152][hw]
    const float* __restrict__ dww,      // [1152][9]
    float* __restrict__ gwin)
{
    __shared__ float h2[2][34 * HSTR];
    __shared__ float s_dww[144 * 9];

    const int tid  = threadIdx.x;
    const int tile = blockIdx.x;           // 0..63
    const int head = blockIdx.y;
    const int b    = blockIdx.z;
    const int tyb = tile >> 3, txb = tile & 7;
    const int y0 = tyb * 32 - 1, x0 = txb * 32 - 1;
    const bool interior = (tyb >= 1) && (tyb <= 6) && (txb >= 1) && (txb <= 6);

    const uint32_t h2a = smem_u32(h2);

    // weights for this head's 144 channels
    for (int e = tid; e < 144 * 9; e += 256) {
        const int l = e / 9, kk = e - l * 9;
        const int z = l / 48, cl = l - z * 48;
        s_dww[e] = dww[(size_t)(z * DIMC + head * CPH + cl) * 9 + kk];
    }

    const size_t bbase = (size_t)b * QKV_M * HW;
    auto srcp = [&](int ch) -> const float* {
        const int gc = (ch / 48) * DIMC + head * CPH + (ch % 48);
        return qkv1 + bbase + (size_t)gc * HW;
    };

    auto issue = [&](int ch, int buf) {
        if (interior) {
            const float* s = srcp(ch) + (size_t)y0 * 256 + (x0 - 3);
            for (int i = tid; i < 340; i += 256) {
                const int r = i / 10, seg = i - r * 10;
                CP_ASYNC16(h2a + (uint32_t)(buf * (34 * HSTR) + r * HSTR + seg * 4) * 4,
                           s + (size_t)r * 256 + seg * 4);
            }
        } else {
            const float* s = srcp(ch);
            for (int i = tid; i < 34 * 34; i += 256) {
                const int r = i / 34, c = i - r * 34;
                const int gy = y0 + r, gx = x0 + c;
                float v = 0.f;
                if ((unsigned)gy < (unsigned)HH && (unsigned)gx < (unsigned)WW)
                    v = s[(size_t)gy * 256 + gx];
                h2[buf][r * HSTR + c + 3] = v;
            }
        }
    };

    issue(0, 0);
    CP_COMMIT();

    const int orow = tid >> 3;             // 0..31
    const int xq   = (tid & 7) * 4;        // 0,4,...,28
    const int wy_l = orow >> 3, wx_l = xq >> 3;
    const int win = (tyb * 4 + wy_l) * 32 + txb * 4 + wx_l;
    float* wbase = gwin + (((size_t)(b * HEADS + head) * 1024 + win) * 144) * 64
                 + (orow & 7) * 8 + (xq & 7);

#pragma unroll 1
    for (int ch = 0; ch < 144; ch++) {
        if (ch + 1 < 144) issue(ch + 1, (ch + 1) & 1);
        CP_COMMIT();
        CP_WAIT1();
        __syncthreads();

        const float* hb = h2[ch & 1] + orow * HSTR + xq + 3;
        const float* wp = s_dww + ch * 9;
        float w[9];
#pragma unroll
        for (int i = 0; i < 9; i++) w[i] = wp[i];
        float a[3][6];
#pragma unroll
        for (int dy = 0; dy < 3; dy++)
#pragma unroll
            for (int c = 0; c < 6; c++) a[dy][c] = hb[dy * HSTR + c];
        float4 o;
        o.x = a[0][0]*w[0] + a[0][1]*w[1] + a[0][2]*w[2]
            + a[1][0]*w[3] + a[1][1]*w[4] + a[1][2]*w[5]
            + a[2][0]*w[6] + a[2][1]*w[7] + a[2][2]*w[8];
        o.y = a[0][1]*w[0] + a[0][2]*w[1] + a[0][3]*w[2]
            + a[1][1]*w[3] + a[1][2]*w[4] + a[1][3]*w[5]
            + a[2][1]*w[6] + a[2][2]*w[7] + a[2][3]*w[8];
        o.z = a[0][2]*w[0] + a[0][3]*w[1] + a[0][4]*w[2]
            + a[1][2]*w[3] + a[1][3]*w[4] + a[1][4]*w[5]
            + a[2][2]*w[6] + a[2][3]*w[7] + a[2][4]*w[8];
        o.w = a[0][3]*w[0] + a[0][4]*w[1] + a[0][5]*w[2]
            + a[1][3]*w[3] + a[1][4]*w[4] + a[1][5]*w[5]
            + a[2][3]*w[6] + a[2][4]*w[7] + a[2][5]*w[8];
        *reinterpret_cast<float4*>(wbase + (size_t)ch * 64) = o;
        __syncthreads();
    }
}

// ---------------- window channel-attention (reads window-major qkv) ----------
#define SQ 68
#define S_ATTN_STRIDE 49
#define A_OFF_QKV  0                         // 144*68 = 9792 floats
#define A_OFF_ATTN 9792                      // 48*49  = 2352
#define A_SMEM_FLOATS (9792 + 2352)          // 12144
#define A_SMEM_BYTES  (A_SMEM_FLOATS * 4)    // 48576

__global__ __launch_bounds__(256) void attn_kernel(
    const float* __restrict__ gwin,          // [(b*8+head)*1024+win][144][64]
    const float* __restrict__ temperature,
    __nv_bfloat16* __restrict__ out_hi,      // [b][hw][384]
    __nv_bfloat16* __restrict__ out_lo)
{
    extern __shared__ float sm[];
    float* s_qkv  = sm + A_OFF_QKV;          // 144 x SQ
    float* s_attn = sm + A_OFF_ATTN;         // 48 x 49
    const uint32_t sqa = smem_u32(s_qkv);

    const int tid  = threadIdx.x;
    const int win  = blockIdx.x;
    const int head = blockIdx.y;
    const int b    = blockIdx.z;
    const int wy = win >> 5, wx = win & 31;

    // ---- cp.async the full 144x64 f32 block (contiguous 36 KB) ----
    const float* base = gwin + (((size_t)(b * HEADS + head) * 1024 + win) * 144) * 64;
#pragma unroll
    for (int it = 0; it < 9; it++) {
        const int i = tid + it * 256;        // 0..2303 chunks of 16B
        const int row = i >> 4, col = (i & 15) * 4;
        CP_ASYNC16(sqa + (uint32_t)(row * SQ + col) * 4, base + (size_t)i * 4);
    }
    CP_COMMIT();
    CP_WAIT0();
    __syncthreads();

    // ---- L2 normalize q,k (96 rows of 64); 8 lanes per row ----
    {
        const int grp = tid >> 3;
        const int gl  = tid & 7;
#pragma unroll
        for (int it = 0; it < 3; it++) {
            const int r = grp + it * 32;
            float* rp = s_qkv + r * SQ + gl * 8;
            float4 v0 = *reinterpret_cast<float4*>(rp);
            float4 v1 = *reinterpret_cast<float4*>(rp + 4);
            float s = v0.x * v0.x + v0.y * v0.y + v0.z * v0.z + v0.w * v0.w
                    + v1.x * v1.x + v1.y * v1.y + v1.z * v1.z + v1.w * v1.w;
            s += __shfl_xor_sync(0xffffffffu, s, 1);
            s += __shfl_xor_sync(0xffffffffu, s, 2);
            s += __shfl_xor_sync(0xffffffffu, s, 4);
            const float inv = 1.f / fmaxf(sqrtf(s), 1e-12f);
            v0.x *= inv; v0.y *= inv; v0.z *= inv; v0.w *= inv;
            v1.x *= inv; v1.y *= inv; v1.z *= inv; v1.w *= inv;
            *reinterpret_cast<float4*>(rp)     = v0;
            *reinterpret_cast<float4*>(rp + 4) = v1;
        }
    }
    __syncthreads();

    const float temp = __ldg(&temperature[head]);

    // ---- attn[c][d] = (q_c . k_d) * temp ----
    {
        const int ty = tid >> 4, tx = tid & 15;
        float acc[3][3];
#pragma unroll
        for (int i = 0; i < 3; i++)
#pragma unroll
            for (int j = 0; j < 3; j++) acc[i][j] = 0.f;
        const float* qb = s_qkv + (ty * 3) * SQ;
        const float* kb = s_qkv + (48 + tx * 3) * SQ;
#pragma unroll 4
        for (int n = 0; n < 64; n += 4) {
            const float4 q0 = *reinterpret_cast<const float4*>(qb + n);
            const float4 q1 = *reinterpret_cast<const float4*>(qb + SQ + n);
            const float4 q2 = *reinterpret_cast<const float4*>(qb + 2 * SQ + n);
            const float4 k0 = *reinterpret_cast<const float4*>(kb + n);
            const float4 k1 = *reinterpret_cast<const float4*>(kb + SQ + n);
            const float4 k2 = *reinterpret_cast<const float4*>(kb + 2 * SQ + n);
            acc[0][0] += q0.x*k0.x + q0.y*k0.y + q0.z*k0.z + q0.w*k0.w;
            acc[0][1] += q0.x*k1.x + q0.y*k1.y + q0.z*k1.z + q0.w*k1.w;
            acc[0][2] += q0.x*k2.x + q0.y*k2.y + q0.z*k2.z + q0.w*k2.w;
            acc[1][0] += q1.x*k0.x + q1.y*k0.y + q1.z*k0.z + q1.w*k0.w;
            acc[1][1] += q1.x*k1.x + q1.y*k1.y + q1.z*k1.z + q1.w*k1.w;
            acc[1][2] += q1.x*k2.x + q1.y*k2.y + q1.z*k2.z + q1.w*k2.w;
            acc[2][0] += q2.x*k0.x + q2.y*k0.y + q2.z*k0.z + q2.w*k0.w;
            acc[2][1] += q2.x*k1.x + q2.y*k1.y + q2.z*k1.z + q2.w*k1.w;
            acc[2][2] += q2.x*k2.x + q2.y*k2.y + q2.z*k2.z + q2.w*k2.w;
        }
#pragma unroll
        for (int i = 0; i < 3; i++)
#pragma unroll
            for (int j = 0; j < 3; j++)
                s_attn[(ty * 3 + i) * S_ATTN_STRIDE + tx * 3 + j] = acc[i][j] * temp;
    }
    __syncthreads();

    // ---- softmax over d ----
    {
        const int warp = tid >> 5, lane = tid & 31;
        for (int r = warp; r < 48; r += 8) {
            const float v0 = s_attn[r * S_ATTN_STRIDE + lane];
            const float v1 = (lane < 16) ? s_attn[r * S_ATTN_STRIDE + lane + 32] : -1e30f;
            float m = fmaxf(v0, v1);
#pragma unroll
            for (int off = 16; off; off >>= 1) m = fmaxf(m, __shfl_xor_sync(0xffffffffu, m, off));
            const float e0 = __expf(v0 - m);
            const float e1 = (lane < 16) ? __expf(v1 - m) : 0.f;
            float s = e0 + e1;
#pragma unroll
            for (int off = 16; off; off >>= 1) s += __shfl_xor_sync(0xffffffffu, s, off);
            const float inv = 1.f / s;
            s_attn[r * S_ATTN_STRIDE + lane] = e0 * inv;
            if (lane < 16) s_attn[r * S_ATTN_STRIDE + lane + 32] = e1 * inv;
        }
    }
    __syncthreads();

    // ---- out[c][n] = sum_d attn[c][d] * v[d][n] -> overwrite q rows --------
    float* s_out = s_qkv;   // rows 0..47 (q no longer needed)
    {
        const int ty = tid >> 4, tx = tid & 15;
        float4 a0c = make_float4(0.f, 0.f, 0.f, 0.f);
        float4 a1c = a0c, a2c = a0c;
        const float* ar0 = s_attn + (ty * 3 + 0) * S_ATTN_STRIDE;
        const float* ar1 = s_attn + (ty * 3 + 1) * S_ATTN_STRIDE;
        const float* ar2 = s_attn + (ty * 3 + 2) * S_ATTN_STRIDE;
#pragma unroll 4
        for (int d = 0; d < 48; ++d) {
            const float a0 = ar0[d], a1 = ar1[d], a2 = ar2[d];
            const float4 v = *reinterpret_cast<const float4*>(&s_qkv[(96 + d) * SQ + tx * 4]);
            a0c.x += a0 * v.x; a0c.y += a0 * v.y; a0c.z += a0 * v.z; a0c.w += a0 * v.w;
            a1c.x += a1 * v.x; a1c.y += a1 * v.y; a1c.z += a1 * v.z; a1c.w += a1 * v.w;
            a2c.x += a2 * v.x; a2c.y += a2 * v.y; a2c.z += a2 * v.z; a2c.w += a2 * v.w;
        }
        __syncthreads();   // q reads fully done before overwrite (QK used them earlier)
        *reinterpret_cast<float4*>(&s_out[(ty * 3 + 0) * SQ + tx * 4]) = a0c;
        *reinterpret_cast<float4*>(&s_out[(ty * 3 + 1) * SQ + tx * 4]) = a1c;
        *reinterpret_cast<float4*>(&s_out[(ty * 3 + 2) * SQ + tx * 4]) = a2c;
    }
    __syncthreads();

    // ---- write bf16 hi/lo to [b][hw][384] ----
    for (int e = tid; e < 1536; e += 256) {
        const int c2 = e % 24;
        const int n  = e / 24;
        const int c  = c2 * 2;
        const float va = s_qkv[c * SQ + n];
        const float vb = s_qkv[(c + 1) * SQ + n];
        const int yy = n >> 3, xx = n & 7;
        const int hw = ((wy * 8 + yy) << 8) + wx * 8 + xx;
        const size_t off = ((size_t)b * HW + hw) * DIMC + head * CPH + c;
        const __nv_bfloat16 ha = __float2bfloat16(va);
        const __nv_bfloat16 hb = __float2bfloat16(vb);
        __nv_bfloat162 hi2, lo2;
        hi2.x = ha; hi2.y = hb;
        lo2.x = __float2bfloat16(va - __bfloat162float(ha));
        lo2.y = __float2bfloat16(vb - __bfloat162float(hb));
        *reinterpret_cast<__nv_bfloat162*>(&out_hi[off]) = hi2;
        *reinterpret_cast<__nv_bfloat162*>(&out_lo[off]) = lo2;
    }
}

// ---------------- launch ----------------------------------------------------
extern "C" void kernel_launch(void* const* d_in, const int* in_sizes, int n_in,
                              void* d_out, int out_size)
{
    const float* x      = (const float*)d_in[0];
    const float* qkv_w  = (const float*)d_in[1];
    const float* dw_w   = (const float*)d_in[2];
    const float* temp   = (const float*)d_in[3];
    const float* proj_w = (const float*)d_in[4];
    const float* proj_b = (const float*)d_in[5];
    float* out = (float*)d_out;

    float *qkv_buf, *win_buf;
    __nv_bfloat16 *xt_hi, *xt_lo, *at_hi, *at_lo, *wq_hi, *wq_lo, *wp_hi, *wp_lo;
    cudaGetSymbolAddress((void**)&qkv_buf, g_qkv);
    cudaGetSymbolAddress((void**)&win_buf, g_win);
    cudaGetSymbolAddress((void**)&xt_hi, g_xt_hi);
    cudaGetSymbolAddress((void**)&xt_lo, g_xt_lo);
    cudaGetSymbolAddress((void**)&at_hi, g_at_hi);
    cudaGetSymbolAddress((void**)&at_lo, g_at_lo);
    cudaGetSymbolAddress((void**)&wq_hi, g_wq_hi);
    cudaGetSymbolAddress((void**)&wq_lo, g_wq_lo);
    cudaGetSymbolAddress((void**)&wp_hi, g_wp_hi);
    cudaGetSymbolAddress((void**)&wp_lo, g_wp_lo);

    cudaFuncSetAttribute(attn_kernel, cudaFuncAttributeMaxDynamicSharedMemorySize, A_SMEM_BYTES);
    cudaFuncSetAttribute(hmma_gemm<0>, cudaFuncAttributeMaxDynamicSharedMemorySize, HG_SMEM);
    cudaFuncSetAttribute(hmma_gemm<1>, cudaFuncAttributeMaxDynamicSharedMemorySize, HG_SMEM);

    // weight splits
    split_w<<<(QKV_M * DIMC + 255) / 256, 256>>>(qkv_w, wq_hi, wq_lo, QKV_M * DIMC);
    split_w<<<(DIMC * DIMC + 255) / 256, 256>>>(proj_w, wp_hi, wp_lo, DIMC * DIMC);

    // x -> transposed hi/lo bf16 [b][hw][384]
    transpose_split<<<dim3(HW / 32, DIMC / 32, BATCH), 256>>>(x, xt_hi, xt_lo, DIMC, HW);

    // qkv = W_qkv . x   -> g_qkv [b][1152][hw] f32
    hmma_gemm<0><<<dim3(QKV_M / 128, HW / 128, BATCH), 256, HG_SMEM>>>(
        wq_hi, wq_lo, xt_hi, xt_lo, qkv_buf, QKV_M, HW, DIMC, nullptr);

    // depthwise 3x3 -> window-major layout
    dwconv_kernel<<<dim3(64, HEADS, BATCH), 256>>>(qkv_buf, dw_w, win_buf);

    // window channel attention -> bf16 hi/lo [b][hw][384]
    attn_kernel<<<dim3(1024, HEADS, BATCH), 256, A_SMEM_BYTES>>>(
        win_buf, temp, at_hi, at_lo);

    // out = W_proj . att + b
    hmma_gemm<1><<<dim3(DIMC / 128, HW / 128, BATCH), 256, HG_SMEM>>>(
        wp_hi, wp_lo, at_hi, at_lo, out, DIMC, HW, DIMC, proj_b);
}

// round 8
// speedup vs baseline: 3.0333x; 1.1446x over previous
#include <cuda_runtime.h>
#include <cuda_bf16.h>
#include <cstdint>
#include <math.h>

// Problem constants
#define DIMC   384
#define HEADS  8
#define CPH    48
#define HH     256
#define WW     256
#define HW     65536
#define BATCH  2
#define QKV_M  1152        // 3*dim

// ---------------- scratch (device globals) ----------------------------------
__device__ float g_qkv[(size_t)BATCH * QKV_M * HW];           // [b][1152][hw] f32
__device__ float g_win[(size_t)BATCH * HEADS * 1024 * 144 * 64]; // window-major dwconv out
__device__ __nv_bfloat16 g_xt_hi[(size_t)BATCH * HW * DIMC];  // [b][hw][384]
__device__ __nv_bfloat16 g_xt_lo[(size_t)BATCH * HW * DIMC];
__device__ __nv_bfloat16 g_at_hi[(size_t)BATCH * HW * DIMC];
__device__ __nv_bfloat16 g_at_lo[(size_t)BATCH * HW * DIMC];
__device__ __nv_bfloat16 g_wq_hi[QKV_M * DIMC], g_wq_lo[QKV_M * DIMC];
__device__ __nv_bfloat16 g_wp_hi[DIMC * DIMC],  g_wp_lo[DIMC * DIMC];

// ---------------- helpers ----------------------------------------------------
__device__ __forceinline__ uint32_t smem_u32(const void* p) {
    uint32_t a;
    asm("{ .reg .u64 t; cvta.to.shared.u64 t, %1; cvt.u32.u64 %0, t; }" : "=r"(a) : "l"(p));
    return a;
}
#define CP_ASYNC16(saddr, gptr) \
    asm volatile("cp.async.cg.shared.global [%0], [%1], 16;" :: "r"(saddr), "l"(gptr))
#define CP_COMMIT() asm volatile("cp.async.commit_group;" ::: "memory")
#define CP_WAIT2()  asm volatile("cp.async.wait_group 2;" ::: "memory")

#define MBARRIER_INIT(addr, cnt) \
    asm volatile("mbarrier.init.shared.b64 [%0], %1;" :: "r"((uint32_t)(addr)), "r"((uint32_t)(cnt)) : "memory")
#define MBARRIER_EXPECT_TX(addr, bytes) \
    asm volatile("mbarrier.arrive.expect_tx.shared.b64 _, [%0], %1;" :: "r"((uint32_t)(addr)), "r"((uint32_t)(bytes)) : "memory")
#define MBARRIER_WAIT_PARITY(mbar_addr, parity) do { \
    uint32_t _mbar = (uint32_t)(mbar_addr); \
    uint32_t _par = (uint32_t)(parity); \
    uint32_t _done; \
    asm volatile( \
        "{\n\t.reg .pred p;\n\t" \
        "mbarrier.try_wait.parity.shared.b64 p, [%1], %2;\n\t" \
        "selp.b32 %0, 1, 0, p;\n\t}" \
        : "=r"(_done) : "r"(_mbar), "r"(_par) : "memory"); \
    if (!_done) { \
        asm volatile( \
            "{\n\t.reg .pred P1;\n\t" \
            "WL_%=:\n\t" \
            "mbarrier.try_wait.parity.shared.b64 P1, [%0], %1;\n\t" \
            "@P1 bra.uni WD_%=;\n\t" \
            "bra.uni WL_%=;\n\t" \
            "WD_%=:\n\t}" \
            :: "r"(_mbar), "r"(_par) : "memory"); \
    } \
} while (0)
#define BULK_CPY(dst_smem, gsrc, bytes, mbar) \
    asm volatile("cp.async.bulk.shared::cta.global.mbarrier::complete_tx::bytes [%0], [%1], %2, [%3];" \
                 :: "r"((uint32_t)(dst_smem)), "l"(gsrc), "r"((uint32_t)(bytes)), "r"((uint32_t)(mbar)) : "memory")
#define FENCE_PROXY_ASYNC() asm volatile("fence.proxy.async.shared::cta;" ::: "memory")

__device__ __forceinline__ void ldmx4(uint32_t* d, uint32_t addr) {
    asm volatile("ldmatrix.sync.aligned.m8n8.x4.shared.b16 {%0,%1,%2,%3}, [%4];"
                 : "=r"(d[0]), "=r"(d[1]), "=r"(d[2]), "=r"(d[3]) : "r"(addr));
}
__device__ __forceinline__ void mma16816(float* c, const uint32_t* a, uint32_t b0, uint32_t b1) {
    asm volatile("mma.sync.aligned.m16n8k16.row.col.f32.bf16.bf16.f32 "
                 "{%0,%1,%2,%3}, {%4,%5,%6,%7}, {%8,%9}, {%0,%1,%2,%3};"
                 : "+f"(c[0]), "+f"(c[1]), "+f"(c[2]), "+f"(c[3])
                 : "r"(a[0]), "r"(a[1]), "r"(a[2]), "r"(a[3]), "r"(b0), "r"(b1));
}
__device__ __forceinline__ uint32_t swz(int r, int cb) {
    return (uint32_t)(r * 64 + ((cb ^ ((r >> 1) & 3)) << 4));
}

// ---------------- transpose + hi/lo bf16 split (for x only) ------------------
__global__ __launch_bounds__(256) void transpose_split(
    const float* __restrict__ in, __nv_bfloat16* __restrict__ hi,
    __nv_bfloat16* __restrict__ lo, int C, int N)
{
    __shared__ float t[32][33];
    const int n0 = blockIdx.x * 32, c0 = blockIdx.y * 32;
    const size_t base = (size_t)blockIdx.z * C * N;
    const int tx = threadIdx.x & 31, ty = threadIdx.x >> 5;
#pragma unroll
    for (int i = 0; i < 4; i++) {
        const int c = ty + i * 8;
        t[c][tx] = in[base + (size_t)(c0 + c) * N + n0 + tx];
    }
    __syncthreads();
#pragma unroll
    for (int i = 0; i < 4; i++) {
        const int n = ty + i * 8;
        const float v = t[tx][n];
        const __nv_bfloat16 h = __float2bfloat16(v);
        const size_t o = base + (size_t)(n0 + n) * C + c0 + tx;
        hi[o] = h;
        lo[o] = __float2bfloat16(v - __bfloat162float(h));
    }
}

__global__ void split_w(const float* __restrict__ w, __nv_bfloat16* __restrict__ hi,
                        __nv_bfloat16* __restrict__ lo, int n)
{
    const int i = blockIdx.x * 256 + threadIdx.x;
    if (i < n) {
        const float v = w[i];
        const __nv_bfloat16 h = __float2bfloat16(v);
        hi[i] = h;
        lo[i] = __float2bfloat16(v - __bfloat162float(h));
    }
}

// ---------------- HMMA GEMM: C[M,N] = A[M,K] . B[N,K]^T ---------------------
#define HG_SMEM 98304

template <int WITH_BIAS>
__global__ __launch_bounds__(256) void hmma_gemm(
    const __nv_bfloat16* __restrict__ Ahi, const __nv_bfloat16* __restrict__ Alo,
    const __nv_bfloat16* __restrict__ Bhi, const __nv_bfloat16* __restrict__ Blo,
    float* __restrict__ Cg, int M, int N, int K, const float* __restrict__ bias)
{
    extern __shared__ char smem[];
    const uint32_t sb = smem_u32(smem);
    const int tid = threadIdx.x;
    const int wid = tid >> 5, lane = tid & 31;
    const int bM = blockIdx.x * 128;
    const int bN = blockIdx.y * 128;
    const size_t bb = (size_t)blockIdx.z * (size_t)N * K;
    float* Cp = Cg + (size_t)blockIdx.z * (size_t)M * N;

    const __nv_bfloat16* Ah = Ahi + (size_t)bM * K;
    const __nv_bfloat16* Al = Alo + (size_t)bM * K;
    const __nv_bfloat16* Bh = Bhi + bb + (size_t)bN * K;
    const __nv_bfloat16* Bl = Blo + bb + (size_t)bN * K;

    const int cb = tid & 3;
    const int r0 = tid >> 2;
    const int nst = K / 32;

#pragma unroll
    for (int ps = 0; ps < 2; ps++) {
        const uint32_t st = sb + ps * 32768;
        const int kk = ps * 32 + cb * 8;
#pragma unroll
        for (int i = 0; i < 2; i++) {
            const int r = r0 + i * 64;
            const uint32_t so = swz(r, cb);
            CP_ASYNC16(st + so,         Ah + (size_t)r * K + kk);
            CP_ASYNC16(st + 8192 + so,  Al + (size_t)r * K + kk);
            CP_ASYNC16(st + 16384 + so, Bh + (size_t)r * K + kk);
            CP_ASYNC16(st + 24576 + so, Bl + (size_t)r * K + kk);
        }
        CP_COMMIT();
    }

    float acc[4][4][4];
#pragma unroll
    for (int i = 0; i < 4; i++)
#pragma unroll
        for (int j = 0; j < 4; j++)
#pragma unroll
            for (int k = 0; k < 4; k++) acc[i][j][k] = 0.f;

    const int wm = (wid >> 2) * 64;
    const int wn = (wid & 3) * 32;
    const int a_rbase = wm + ((lane >> 3) & 1) * 8 + (lane & 7);
    const int a_cbad  = lane >> 4;
    const int b_rbase = wn + ((lane >> 4) & 1) * 8 + (lane & 7);
    const int b_cbad  = (lane >> 3) & 1;

    int sidx = 0;
    for (int s = 0; s < nst; s++) {
        if (s + 2 < nst) {
            int fi = sidx + 2; if (fi >= 3) fi -= 3;
            const uint32_t st = sb + fi * 32768;
            const int kk = (s + 2) * 32 + cb * 8;
#pragma unroll
            for (int i = 0; i < 2; i++) {
                const int r = r0 + i * 64;
                const uint32_t so = swz(r, cb);
                CP_ASYNC16(st + so,         Ah + (size_t)r * K + kk);
                CP_ASYNC16(st + 8192 + so,  Al + (size_t)r * K + kk);
                CP_ASYNC16(st + 16384 + so, Bh + (size_t)r * K + kk);
                CP_ASYNC16(st + 24576 + so, Bl + (size_t)r * K + kk);
            }
        }
        CP_COMMIT();
        CP_WAIT2();
        __syncthreads();

        const uint32_t st = sb + sidx * 32768;
#pragma unroll
        for (int k16 = 0; k16 < 2; k16++) {
            uint32_t bhf[2][4], blf[2][4];
#pragma unroll
            for (int nh = 0; nh < 2; nh++) {
                const uint32_t ad = st + 16384 + swz(b_rbase + nh * 16, k16 * 2 + b_cbad);
                ldmx4(bhf[nh], ad);
                ldmx4(blf[nh], ad + 8192);
            }
#pragma unroll
            for (int mh = 0; mh < 4; mh++) {
                uint32_t ahf[4], alf[4];
                const uint32_t ad = st + swz(a_rbase + mh * 16, k16 * 2 + a_cbad);
                ldmx4(ahf, ad);
                ldmx4(alf, ad + 8192);
#pragma unroll
                for (int nb = 0; nb < 4; nb++) {
                    const uint32_t* fh = &bhf[nb >> 1][(nb & 1) * 2];
                    const uint32_t* fl = &blf[nb >> 1][(nb & 1) * 2];
                    mma16816(acc[mh][nb], ahf, fh[0], fh[1]);
                    mma16816(acc[mh][nb], ahf, fl[0], fl[1]);
                    mma16816(acc[mh][nb], alf, fh[0], fh[1]);
                }
            }
        }
        __syncthreads();
        if (++sidx == 3) sidx = 0;
    }

    const int row0 = bM + wm + (lane >> 2);
    const int col0 = bN + wn + (lane & 3) * 2;
#pragma unroll
    for (int mh = 0; mh < 4; mh++) {
#pragma unroll
        for (int p = 0; p < 2; p++) {
            const int row = row0 + mh * 16 + p * 8;
            const float bi = WITH_BIAS ? __ldg(&bias[row]) : 0.f;
#pragma unroll
            for (int nb = 0; nb < 4; nb++) {
                float2 v;
                v.x = acc[mh][nb][p * 2 + 0] + bi;
                v.y = acc[mh][nb][p * 2 + 1] + bi;
                *reinterpret_cast<float2*>(&Cp[(size_t)row * N + col0 + nb * 8]) = v;
            }
        }
    }
}

// ---------------- dwconv 3x3 -> window-major layout (bulk-copy pipeline) -----
// grid (64 tiles of 32x32, 8 heads, 2 batch); 256 threads.
// 4-stage ring of 34x40 halo buffers filled by cp.async.bulk row copies.
#define HSTR 40

__global__ __launch_bounds__(256) void dwconv_kernel(
    const float* __restrict__ qkv1,     // [b][1152][hw]
    const float* __restrict__ dww,      // [1152][9]
    float* __restrict__ gwin)
{
    __shared__ __align__(16) float h4[4][34 * HSTR];
    __shared__ float s_dww[144 * 9];
    __shared__ __align__(8) uint64_t mbar[4];

    const int tid  = threadIdx.x;
    const int tile = blockIdx.x;           // 0..63
    const int head = blockIdx.y;
    const int b    = blockIdx.z;
    const int tyb = tile >> 3, txb = tile & 7;
    const int y0 = tyb * 32 - 1, x0 = txb * 32 - 1;

    // clamped row geometry (identical for every channel)
    const int cs = x0 - 3;                          // global col of buffer col 0
    const int src_off = cs < 0 ? 0 : cs;
    const int dst_off = src_off - cs;               // 0 or 4 floats
    const int cend = (cs + 40 > 256) ? 256 : (cs + 40);
    const uint32_t rowbytes = (uint32_t)(cend - src_off) * 4;   // 160 or 144
    const int r_lo = (y0 < 0) ? 1 : 0;
    const int r_hi = (y0 + 33 > 255) ? 32 : 33;
    const uint32_t expect = (uint32_t)(r_hi - r_lo + 1) * rowbytes;

    // weights for this head's 144 channels
    for (int e = tid; e < 144 * 9; e += 256) {
        const int l = e / 9, kk = e - l * 9;
        const int z = l / 48, cl = l - z * 48;
        s_dww[e] = dww[(size_t)(z * DIMC + head * CPH + cl) * 9 + kk];
    }
    // zero ring buffers (edge padding persists across channels)
    for (int e = tid; e < 4 * 34 * HSTR; e += 256) (&h4[0][0])[e] = 0.f;
    if (tid < 4) MBARRIER_INIT(smem_u32(&mbar[tid]), 1);
    __syncthreads();
    FENCE_PROXY_ASYNC();

    const size_t bbase = (size_t)b * QKV_M * HW;
    const int wid = tid >> 5, lane = tid & 31;

    auto issue = [&](int ch) {
        const int st = ch & 3;
        const uint32_t mb = smem_u32(&mbar[st]);
        if (lane == 0) MBARRIER_EXPECT_TX(mb, expect);
        const int gc = (ch / 48) * DIMC + head * CPH + (ch % 48);
        const float* srcc = qkv1 + bbase + (size_t)gc * HW;
        const uint32_t dbase = smem_u32(&h4[st][0]);
        for (int r = lane; r < 34; r += 32) {
            if (r >= r_lo && r <= r_hi) {
                BULK_CPY(dbase + (uint32_t)(r * HSTR + dst_off) * 4,
                         srcc + (size_t)(y0 + r) * 256 + src_off,
                         rowbytes, mb);
            }
        }
    };
    if (wid == 0) { issue(0); issue(1); issue(2); }

    const int orow = tid >> 3;             // 0..31
    const int xq   = (tid & 7) * 4;        // 0,4,...,28
    const int wy_l = orow >> 3, wx_l = xq >> 3;
    const int win = (tyb * 4 + wy_l) * 32 + txb * 4 + wx_l;
    float* wbase = gwin + (((size_t)(b * HEADS + head) * 1024 + win) * 144) * 64
                 + (orow & 7) * 8 + (xq & 7);

#pragma unroll 1
    for (int ch = 0; ch < 144; ch++) {
        if (wid == 0 && ch + 3 < 144) issue(ch + 3);
        MBARRIER_WAIT_PARITY(smem_u32(&mbar[ch & 3]), (ch >> 2) & 1);

        const float* hb = h4[ch & 3] + orow * HSTR + xq + 3;
        const float* wp = s_dww + ch * 9;
        float w[9];
#pragma unroll
        for (int i = 0; i < 9; i++) w[i] = wp[i];
        float a[3][6];
#pragma unroll
        for (int dy = 0; dy < 3; dy++)
#pragma unroll
            for (int c = 0; c < 6; c++) a[dy][c] = hb[dy * HSTR + c];
        float4 o;
        o.x = a[0][0]*w[0] + a[0][1]*w[1] + a[0][2]*w[2]
            + a[1][0]*w[3] + a[1][1]*w[4] + a[1][2]*w[5]
            + a[2][0]*w[6] + a[2][1]*w[7] + a[2][2]*w[8];
        o.y = a[0][1]*w[0] + a[0][2]*w[1] + a[0][3]*w[2]
            + a[1][1]*w[3] + a[1][2]*w[4] + a[1][3]*w[5]
            + a[2][1]*w[6] + a[2][2]*w[7] + a[2][3]*w[8];
        o.z = a[0][2]*w[0] + a[0][3]*w[1] + a[0][4]*w[2]
            + a[1][2]*w[3] + a[1][3]*w[4] + a[1][4]*w[5]
            + a[2][2]*w[6] + a[2][3]*w[7] + a[2][4]*w[8];
        o.w = a[0][3]*w[0] + a[0][4]*w[1] + a[0][5]*w[2]
            + a[1][3]*w[3] + a[1][4]*w[4] + a[1][5]*w[5]
            + a[2][3]*w[6] + a[2][4]*w[7] + a[2][5]*w[8];
        *reinterpret_cast<float4*>(wbase + (size_t)ch * 64) = o;
        __syncthreads();
    }
}

// ---------------- window channel-attention (reads window-major qkv) ----------
#define SQ 68
#define S_ATTN_STRIDE 49
#define A_OFF_QKV  0                         // 144*68 = 9792 floats
#define A_OFF_ATTN 9792                      // 48*49  = 2352
#define A_SMEM_FLOATS (9792 + 2352)          // 12144
#define A_SMEM_BYTES  (A_SMEM_FLOATS * 4)    // 48576

__global__ __launch_bounds__(256) void attn_kernel(
    const float* __restrict__ gwin,          // [(b*8+head)*1024+win][144][64]
    const float* __restrict__ temperature,
    __nv_bfloat16* __restrict__ out_hi,      // [b][hw][384]
    __nv_bfloat16* __restrict__ out_lo)
{
    extern __shared__ float sm[];
    float* s_qkv  = sm + A_OFF_QKV;          // 144 x SQ
    float* s_attn = sm + A_OFF_ATTN;         // 48 x 49
    __shared__ __align__(8) uint64_t a_mbar;
    const uint32_t sqa = smem_u32(s_qkv);

    const int tid  = threadIdx.x;
    const int win  = blockIdx.x;
    const int head = blockIdx.y;
    const int b    = blockIdx.z;
    const int wy = win >> 5, wx = win & 31;

    // ---- bulk-copy the 144x64 f32 block: one 256B copy per row ----
    if (tid == 0) MBARRIER_INIT(smem_u32(&a_mbar), 1);
    __syncthreads();
    const float* base = gwin + (((size_t)(b * HEADS + head) * 1024 + win) * 144) * 64;
    if (tid < 32) {
        const uint32_t mb = smem_u32(&a_mbar);
        if (tid == 0) MBARRIER_EXPECT_TX(mb, 144 * 256);
        for (int r = tid; r < 144; r += 32)
            BULK_CPY(sqa + (uint32_t)(r * SQ) * 4, base + (size_t)r * 64, 256, mb);
    }
    MBARRIER_WAIT_PARITY(smem_u32(&a_mbar), 0);

    // ---- L2 normalize q,k (96 rows of 64); 8 lanes per row ----
    {
        const int grp = tid >> 3;
        const int gl  = tid & 7;
#pragma unroll
        for (int it = 0; it < 3; it++) {
            const int r = grp + it * 32;
            float* rp = s_qkv + r * SQ + gl * 8;
            float4 v0 = *reinterpret_cast<float4*>(rp);
            float4 v1 = *reinterpret_cast<float4*>(rp + 4);
            float s = v0.x * v0.x + v0.y * v0.y + v0.z * v0.z + v0.w * v0.w
                    + v1.x * v1.x + v1.y * v1.y + v1.z * v1.z + v1.w * v1.w;
            s += __shfl_xor_sync(0xffffffffu, s, 1);
            s += __shfl_xor_sync(0xffffffffu, s, 2);
            s += __shfl_xor_sync(0xffffffffu, s, 4);
            const float inv = 1.f / fmaxf(sqrtf(s), 1e-12f);
            v0.x *= inv; v0.y *= inv; v0.z *= inv; v0.w *= inv;
            v1.x *= inv; v1.y *= inv; v1.z *= inv; v1.w *= inv;
            *reinterpret_cast<float4*>(rp)     = v0;
            *reinterpret_cast<float4*>(rp + 4) = v1;
        }
    }
    __syncthreads();

    const float temp = __ldg(&temperature[head]);

    // ---- attn[c][d] = (q_c . k_d) * temp ----
    {
        const int ty = tid >> 4, tx = tid & 15;
        float acc[3][3];
#pragma unroll
        for (int i = 0; i < 3; i++)
#pragma unroll
            for (int j = 0; j < 3; j++) acc[i][j] = 0.f;
        const float* qb = s_qkv + (ty * 3) * SQ;
        const float* kb = s_qkv + (48 + tx * 3) * SQ;
#pragma unroll 4
        for (int n = 0; n < 64; n += 4) {
            const float4 q0 = *reinterpret_cast<const float4*>(qb + n);
            const float4 q1 = *reinterpret_cast<const float4*>(qb + SQ + n);
            const float4 q2 = *reinterpret_cast<const float4*>(qb + 2 * SQ + n);
            const float4 k0 = *reinterpret_cast<const float4*>(kb + n);
            const float4 k1 = *reinterpret_cast<const float4*>(kb + SQ + n);
            const float4 k2 = *reinterpret_cast<const float4*>(kb + 2 * SQ + n);
            acc[0][0] += q0.x*k0.x + q0.y*k0.y + q0.z*k0.z + q0.w*k0.w;
            acc[0][1] += q0.x*k1.x + q0.y*k1.y + q0.z*k1.z + q0.w*k1.w;
            acc[0][2] += q0.x*k2.x + q0.y*k2.y + q0.z*k2.z + q0.w*k2.w;
            acc[1][0] += q1.x*k0.x + q1.y*k0.y + q1.z*k0.z + q1.w*k0.w;
            acc[1][1] += q1.x*k1.x + q1.y*k1.y + q1.z*k1.z + q1.w*k1.w;
            acc[1][2] += q1.x*k2.x + q1.y*k2.y + q1.z*k2.z + q1.w*k2.w;
            acc[2][0] += q2.x*k0.x + q2.y*k0.y + q2.z*k0.z + q2.w*k0.w;
            acc[2][1] += q2.x*k1.x + q2.y*k1.y + q2.z*k1.z + q2.w*k1.w;
            acc[2][2] += q2.x*k2.x + q2.y*k2.y + q2.z*k2.z + q2.w*k2.w;
        }
#pragma unroll
        for (int i = 0; i < 3; i++)
#pragma unroll
            for (int j = 0; j < 3; j++)
                s_attn[(ty * 3 + i) * S_ATTN_STRIDE + tx * 3 + j] = acc[i][j] * temp;
    }
    __syncthreads();

    // ---- softmax over d ----
    {
        const int warp = tid >> 5, lane = tid & 31;
        for (int r = warp; r < 48; r += 8) {
            const float v0 = s_attn[r * S_ATTN_STRIDE + lane];
            const float v1 = (lane < 16) ? s_attn[r * S_ATTN_STRIDE + lane + 32] : -1e30f;
            float m = fmaxf(v0, v1);
#pragma unroll
            for (int off = 16; off; off >>= 1) m = fmaxf(m, __shfl_xor_sync(0xffffffffu, m, off));
            const float e0 = __expf(v0 - m);
            const float e1 = (lane < 16) ? __expf(v1 - m) : 0.f;
            float s = e0 + e1;
#pragma unroll
            for (int off = 16; off; off >>= 1) s += __shfl_xor_sync(0xffffffffu, s, off);
            const float inv = 1.f / s;
            s_attn[r * S_ATTN_STRIDE + lane] = e0 * inv;
            if (lane < 16) s_attn[r * S_ATTN_STRIDE + lane + 32] = e1 * inv;
        }
    }
    __syncthreads();

    // ---- out[c][n] = sum_d attn[c][d] * v[d][n] -> overwrite q rows --------
    float* s_out = s_qkv;
    {
        const int ty = tid >> 4, tx = tid & 15;
        float4 a0c = make_float4(0.f, 0.f, 0.f, 0.f);
        float4 a1c = a0c, a2c = a0c;
        const float* ar0 = s_attn + (ty * 3 + 0) * S_ATTN_STRIDE;
        const float* ar1 = s_attn + (ty * 3 + 1) * S_ATTN_STRIDE;
        const float* ar2 = s_attn + (ty * 3 + 2) * S_ATTN_STRIDE;
#pragma unroll 4
        for (int d = 0; d < 48; ++d) {
            const float a0 = ar0[d], a1 = ar1[d], a2 = ar2[d];
            const float4 v = *reinterpret_cast<const float4*>(&s_qkv[(96 + d) * SQ + tx * 4]);
            a0c.x += a0 * v.x; a0c.y += a0 * v.y; a0c.z += a0 * v.z; a0c.w += a0 * v.w;
            a1c.x += a1 * v.x; a1c.y += a1 * v.y; a1c.z += a1 * v.z; a1c.w += a1 * v.w;
            a2c.x += a2 * v.x; a2c.y += a2 * v.y; a2c.z += a2 * v.z; a2c.w += a2 * v.w;
        }
        __syncthreads();
        *reinterpret_cast<float4*>(&s_out[(ty * 3 + 0) * SQ + tx * 4]) = a0c;
        *reinterpret_cast<float4*>(&s_out[(ty * 3 + 1) * SQ + tx * 4]) = a1c;
        *reinterpret_cast<float4*>(&s_out[(ty * 3 + 2) * SQ + tx * 4]) = a2c;
    }
    __syncthreads();

    // ---- write bf16 hi/lo to [b][hw][384] ----
    for (int e = tid; e < 1536; e += 256) {
        const int c2 = e % 24;
        const int n  = e / 24;
        const int c  = c2 * 2;
        const float va = s_qkv[c * SQ + n];
        const float vb = s_qkv[(c + 1) * SQ + n];
        const int yy = n >> 3, xx = n & 7;
        const int hw = ((wy * 8 + yy) << 8) + wx * 8 + xx;
        const size_t off = ((size_t)b * HW + hw) * DIMC + head * CPH + c;
        const __nv_bfloat16 ha = __float2bfloat16(va);
        const __nv_bfloat16 hb = __float2bfloat16(vb);
        __nv_bfloat162 hi2, lo2;
        hi2.x = ha; hi2.y = hb;
        lo2.x = __float2bfloat16(va - __bfloat162float(ha));
        lo2.y = __float2bfloat16(vb - __bfloat162float(hb));
        *reinterpret_cast<__nv_bfloat162*>(&out_hi[off]) = hi2;
        *reinterpret_cast<__nv_bfloat162*>(&out_lo[off]) = lo2;
    }
}

// ---------------- launch ----------------------------------------------------
extern "C" void kernel_launch(void* const* d_in, const int* in_sizes, int n_in,
                              void* d_out, int out_size)
{
    const float* x      = (const float*)d_in[0];
    const float* qkv_w  = (const float*)d_in[1];
    const float* dw_w   = (const float*)d_in[2];
    const float* temp   = (const float*)d_in[3];
    const float* proj_w = (const float*)d_in[4];
    const float* proj_b = (const float*)d_in[5];
    float* out = (float*)d_out;

    float *qkv_buf, *win_buf;
    __nv_bfloat16 *xt_hi, *xt_lo, *at_hi, *at_lo, *wq_hi, *wq_lo, *wp_hi, *wp_lo;
    cudaGetSymbolAddress((void**)&qkv_buf, g_qkv);
    cudaGetSymbolAddress((void**)&win_buf, g_win);
    cudaGetSymbolAddress((void**)&xt_hi, g_xt_hi);
    cudaGetSymbolAddress((void**)&xt_lo, g_xt_lo);
    cudaGetSymbolAddress((void**)&at_hi, g_at_hi);
    cudaGetSymbolAddress((void**)&at_lo, g_at_lo);
    cudaGetSymbolAddress((void**)&wq_hi, g_wq_hi);
    cudaGetSymbolAddress((void**)&wq_lo, g_wq_lo);
    cudaGetSymbolAddress((void**)&wp_hi, g_wp_hi);
    cudaGetSymbolAddress((void**)&wp_lo, g_wp_lo);

    cudaFuncSetAttribute(attn_kernel, cudaFuncAttributeMaxDynamicSharedMemorySize, A_SMEM_BYTES);
    cudaFuncSetAttribute(hmma_gemm<0>, cudaFuncAttributeMaxDynamicSharedMemorySize, HG_SMEM);
    cudaFuncSetAttribute(hmma_gemm<1>, cudaFuncAttributeMaxDynamicSharedMemorySize, HG_SMEM);

    // weight splits
    split_w<<<(QKV_M * DIMC + 255) / 256, 256>>>(qkv_w, wq_hi, wq_lo, QKV_M * DIMC);
    split_w<<<(DIMC * DIMC + 255) / 256, 256>>>(proj_w, wp_hi, wp_lo, DIMC * DIMC);

    // x -> transposed hi/lo bf16 [b][hw][384]
    transpose_split<<<dim3(HW / 32, DIMC / 32, BATCH), 256>>>(x, xt_hi, xt_lo, DIMC, HW);

    // qkv = W_qkv . x   -> g_qkv [b][1152][hw] f32
    hmma_gemm<0><<<dim3(QKV_M / 128, HW / 128, BATCH), 256, HG_SMEM>>>(
        wq_hi, wq_lo, xt_hi, xt_lo, qkv_buf, QKV_M, HW, DIMC, nullptr);

    // depthwise 3x3 -> window-major layout
    dwconv_kernel<<<dim3(64, HEADS, BATCH), 256>>>(qkv_buf, dw_w, win_buf);

    // window channel attention -> bf16 hi/lo [b][hw][384]
    attn_kernel<<<dim3(1024, HEADS, BATCH), 256, A_SMEM_BYTES>>>(
        win_buf, temp, at_hi, at_lo);

    // out = W_proj . att + b
    hmma_gemm<1><<<dim3(DIMC / 128, HW / 128, BATCH), 256, HG_SMEM>>>(
        wp_hi, wp_lo, at_hi, at_lo, out, DIMC, HW, DIMC, proj_b);
}

// round 9
// speedup vs baseline: 3.0676x; 1.0113x over previous
#include <cuda_runtime.h>
#include <cuda_bf16.h>
#include <cstdint>
#include <math.h>

// Problem constants
#define DIMC   384
#define HEADS  8
#define CPH    48
#define HH     256
#define WW     256
#define HW     65536
#define BATCH  2
#define QKV_M  1152        // 3*dim

// ---------------- scratch (device globals) ----------------------------------
__device__ float g_qkv[(size_t)BATCH * QKV_M * HW];           // [b][1152][hw] f32
__device__ float g_win[(size_t)BATCH * HEADS * 1024 * 144 * 64]; // window-major dwconv out
__device__ __nv_bfloat16 g_xt_hi[(size_t)BATCH * HW * DIMC];  // [b][hw][384]
__device__ __nv_bfloat16 g_xt_lo[(size_t)BATCH * HW * DIMC];
__device__ __nv_bfloat16 g_at_hi[(size_t)BATCH * HW * DIMC];
__device__ __nv_bfloat16 g_at_lo[(size_t)BATCH * HW * DIMC];
__device__ __nv_bfloat16 g_wq_hi[QKV_M * DIMC], g_wq_lo[QKV_M * DIMC];
__device__ __nv_bfloat16 g_wp_hi[DIMC * DIMC],  g_wp_lo[DIMC * DIMC];

// ---------------- helpers ----------------------------------------------------
__device__ __forceinline__ uint32_t smem_u32(const void* p) {
    uint32_t a;
    asm("{ .reg .u64 t; cvta.to.shared.u64 t, %1; cvt.u32.u64 %0, t; }" : "=r"(a) : "l"(p));
    return a;
}
#define CP_ASYNC16(saddr, gptr) \
    asm volatile("cp.async.cg.shared.global [%0], [%1], 16;" :: "r"(saddr), "l"(gptr))
#define CP_COMMIT() asm volatile("cp.async.commit_group;" ::: "memory")
#define CP_WAIT0()  asm volatile("cp.async.wait_group 0;" ::: "memory")
#define CP_WAIT1()  asm volatile("cp.async.wait_group 1;" ::: "memory")

#define MBARRIER_INIT(addr, cnt) \
    asm volatile("mbarrier.init.shared.b64 [%0], %1;" :: "r"((uint32_t)(addr)), "r"((uint32_t)(cnt)) : "memory")
#define MBARRIER_EXPECT_TX(addr, bytes) \
    asm volatile("mbarrier.arrive.expect_tx.shared.b64 _, [%0], %1;" :: "r"((uint32_t)(addr)), "r"((uint32_t)(bytes)) : "memory")
#define MBARRIER_WAIT_PARITY(mbar_addr, parity) do { \
    uint32_t _mbar = (uint32_t)(mbar_addr); \
    uint32_t _par = (uint32_t)(parity); \
    uint32_t _done; \
    asm volatile( \
        "{\n\t.reg .pred p;\n\t" \
        "mbarrier.try_wait.parity.shared.b64 p, [%1], %2;\n\t" \
        "selp.b32 %0, 1, 0, p;\n\t}" \
        : "=r"(_done) : "r"(_mbar), "r"(_par) : "memory"); \
    if (!_done) { \
        asm volatile( \
            "{\n\t.reg .pred P1;\n\t" \
            "WL_%=:\n\t" \
            "mbarrier.try_wait.parity.shared.b64 P1, [%0], %1;\n\t" \
            "@P1 bra.uni WD_%=;\n\t" \
            "bra.uni WL_%=;\n\t" \
            "WD_%=:\n\t}" \
            :: "r"(_mbar), "r"(_par) : "memory"); \
    } \
} while (0)
#define BULK_CPY(dst_smem, gsrc, bytes, mbar) \
    asm volatile("cp.async.bulk.shared::cta.global.mbarrier::complete_tx::bytes [%0], [%1], %2, [%3];" \
                 :: "r"((uint32_t)(dst_smem)), "l"(gsrc), "r"((uint32_t)(bytes)), "r"((uint32_t)(mbar)) : "memory")
#define FENCE_PROXY_ASYNC() asm volatile("fence.proxy.async.shared::cta;" ::: "memory")

__device__ __forceinline__ void ldmx4(uint32_t* d, uint32_t addr) {
    asm volatile("ldmatrix.sync.aligned.m8n8.x4.shared.b16 {%0,%1,%2,%3}, [%4];"
                 : "=r"(d[0]), "=r"(d[1]), "=r"(d[2]), "=r"(d[3]) : "r"(addr));
}
__device__ __forceinline__ void ldmx2(uint32_t* d, uint32_t addr) {
    asm volatile("ldmatrix.sync.aligned.m8n8.x2.shared.b16 {%0,%1}, [%2];"
                 : "=r"(d[0]), "=r"(d[1]) : "r"(addr));
}
__device__ __forceinline__ void mma16816(float* c, const uint32_t* a, uint32_t b0, uint32_t b1) {
    asm volatile("mma.sync.aligned.m16n8k16.row.col.f32.bf16.bf16.f32 "
                 "{%0,%1,%2,%3}, {%4,%5,%6,%7}, {%8,%9}, {%0,%1,%2,%3};"
                 : "+f"(c[0]), "+f"(c[1]), "+f"(c[2]), "+f"(c[3])
                 : "r"(a[0]), "r"(a[1]), "r"(a[2]), "r"(a[3]), "r"(b0), "r"(b1));
}
__device__ __forceinline__ uint32_t swz(int r, int cb) {          // 64B rows (GEMM tiles)
    return (uint32_t)(r * 64 + ((cb ^ ((r >> 1) & 3)) << 4));
}
__device__ __forceinline__ uint32_t swz128r(int r, int cb) {      // 128B rows (attn bf16)
    return (uint32_t)(r * 128 + ((cb ^ (r & 7)) << 4));
}

// ---------------- transpose + hi/lo bf16 split (for x only) ------------------
__global__ __launch_bounds__(256) void transpose_split(
    const float* __restrict__ in, __nv_bfloat16* __restrict__ hi,
    __nv_bfloat16* __restrict__ lo, int C, int N)
{
    __shared__ float t[32][33];
    const int n0 = blockIdx.x * 32, c0 = blockIdx.y * 32;
    const size_t base = (size_t)blockIdx.z * C * N;
    const int tx = threadIdx.x & 31, ty = threadIdx.x >> 5;
#pragma unroll
    for (int i = 0; i < 4; i++) {
        const int c = ty + i * 8;
        t[c][tx] = in[base + (size_t)(c0 + c) * N + n0 + tx];
    }
    __syncthreads();
#pragma unroll
    for (int i = 0; i < 4; i++) {
        const int n = ty + i * 8;
        const float v = t[tx][n];
        const __nv_bfloat16 h = __float2bfloat16(v);
        const size_t o = base + (size_t)(n0 + n) * C + c0 + tx;
        hi[o] = h;
        lo[o] = __float2bfloat16(v - __bfloat162float(h));
    }
}

__global__ void split_w(const float* __restrict__ w, __nv_bfloat16* __restrict__ hi,
                        __nv_bfloat16* __restrict__ lo, int n)
{
    const int i = blockIdx.x * 256 + threadIdx.x;
    if (i < n) {
        const float v = w[i];
        const __nv_bfloat16 h = __float2bfloat16(v);
        hi[i] = h;
        lo[i] = __float2bfloat16(v - __bfloat162float(h));
    }
}

// ---------------- HMMA GEMM: C[M,N] = A[M,K] . B[N,K]^T ---------------------
// CTA tile 128x128, K-stage 32, 3-stage cp.async ring, ONE barrier per stage.
#define HG_SMEM 98304

template <int WITH_BIAS>
__global__ __launch_bounds__(256) void hmma_gemm(
    const __nv_bfloat16* __restrict__ Ahi, const __nv_bfloat16* __restrict__ Alo,
    const __nv_bfloat16* __restrict__ Bhi, const __nv_bfloat16* __restrict__ Blo,
    float* __restrict__ Cg, int M, int N, int K, const float* __restrict__ bias)
{
    extern __shared__ char smem[];
    const uint32_t sb = smem_u32(smem);
    const int tid = threadIdx.x;
    const int wid = tid >> 5, lane = tid & 31;
    const int bM = blockIdx.x * 128;
    const int bN = blockIdx.y * 128;
    const size_t bb = (size_t)blockIdx.z * (size_t)N * K;
    float* Cp = Cg + (size_t)blockIdx.z * (size_t)M * N;

    const __nv_bfloat16* Ah = Ahi + (size_t)bM * K;
    const __nv_bfloat16* Al = Alo + (size_t)bM * K;
    const __nv_bfloat16* Bh = Bhi + bb + (size_t)bN * K;
    const __nv_bfloat16* Bl = Blo + bb + (size_t)bN * K;

    const int cb = tid & 3;
    const int r0 = tid >> 2;
    const int nst = K / 32;

    // ---- prologue: fill stages 0,1 ----
#pragma unroll
    for (int ps = 0; ps < 2; ps++) {
        const uint32_t st = sb + ps * 32768;
        const int kk = ps * 32 + cb * 8;
#pragma unroll
        for (int i = 0; i < 2; i++) {
            const int r = r0 + i * 64;
            const uint32_t so = swz(r, cb);
            CP_ASYNC16(st + so,         Ah + (size_t)r * K + kk);
            CP_ASYNC16(st + 8192 + so,  Al + (size_t)r * K + kk);
            CP_ASYNC16(st + 16384 + so, Bh + (size_t)r * K + kk);
            CP_ASYNC16(st + 24576 + so, Bl + (size_t)r * K + kk);
        }
        CP_COMMIT();
    }

    float acc[4][4][4];
#pragma unroll
    for (int i = 0; i < 4; i++)
#pragma unroll
        for (int j = 0; j < 4; j++)
#pragma unroll
            for (int k = 0; k < 4; k++) acc[i][j][k] = 0.f;

    const int wm = (wid >> 2) * 64;
    const int wn = (wid & 3) * 32;
    const int a_rbase = wm + ((lane >> 3) & 1) * 8 + (lane & 7);
    const int a_cbad  = lane >> 4;
    const int b_rbase = wn + ((lane >> 4) & 1) * 8 + (lane & 7);
    const int b_cbad  = (lane >> 3) & 1;

    int sidx = 0;
    for (int s = 0; s < nst; s++) {
        if (s + 1 < nst) CP_WAIT1(); else CP_WAIT0();   // stage s data resident
        __syncthreads();

        // issue next stage's loads BEFORE compute (overlap with MMA)
        if (s + 2 < nst) {
            int fi = sidx + 2; if (fi >= 3) fi -= 3;
            const uint32_t st = sb + fi * 32768;
            const int kk = (s + 2) * 32 + cb * 8;
#pragma unroll
            for (int i = 0; i < 2; i++) {
                const int r = r0 + i * 64;
                const uint32_t so = swz(r, cb);
                CP_ASYNC16(st + so,         Ah + (size_t)r * K + kk);
                CP_ASYNC16(st + 8192 + so,  Al + (size_t)r * K + kk);
                CP_ASYNC16(st + 16384 + so, Bh + (size_t)r * K + kk);
                CP_ASYNC16(st + 24576 + so, Bl + (size_t)r * K + kk);
            }
            CP_COMMIT();
        }

        const uint32_t st = sb + sidx * 32768;
#pragma unroll
        for (int k16 = 0; k16 < 2; k16++) {
            uint32_t bhf[2][4], blf[2][4];
#pragma unroll
            for (int nh = 0; nh < 2; nh++) {
                const uint32_t ad = st + 16384 + swz(b_rbase + nh * 16, k16 * 2 + b_cbad);
                ldmx4(bhf[nh], ad);
                ldmx4(blf[nh], ad + 8192);
            }
#pragma unroll
            for (int mh = 0; mh < 4; mh++) {
                uint32_t ahf[4], alf[4];
                const uint32_t ad = st + swz(a_rbase + mh * 16, k16 * 2 + a_cbad);
                ldmx4(ahf, ad);
                ldmx4(alf, ad + 8192);
#pragma unroll
                for (int nb = 0; nb < 4; nb++) {
                    const uint32_t* fh = &bhf[nb >> 1][(nb & 1) * 2];
                    const uint32_t* fl = &blf[nb >> 1][(nb & 1) * 2];
                    mma16816(acc[mh][nb], ahf, fh[0], fh[1]);
                    mma16816(acc[mh][nb], ahf, fl[0], fl[1]);
                    mma16816(acc[mh][nb], alf, fh[0], fh[1]);
                }
            }
        }
        if (++sidx == 3) sidx = 0;
    }
    __syncthreads();

    const int row0 = bM + wm + (lane >> 2);
    const int col0 = bN + wn + (lane & 3) * 2;
#pragma unroll
    for (int mh = 0; mh < 4; mh++) {
#pragma unroll
        for (int p = 0; p < 2; p++) {
            const int row = row0 + mh * 16 + p * 8;
            const float bi = WITH_BIAS ? __ldg(&bias[row]) : 0.f;
#pragma unroll
            for (int nb = 0; nb < 4; nb++) {
                float2 v;
                v.x = acc[mh][nb][p * 2 + 0] + bi;
                v.y = acc[mh][nb][p * 2 + 1] + bi;
                *reinterpret_cast<float2*>(&Cp[(size_t)row * N + col0 + nb * 8]) = v;
            }
        }
    }
}

// ---------------- dwconv 3x3 -> window-major layout (bulk-copy pipeline) -----
#define HSTR 40

__global__ __launch_bounds__(256) void dwconv_kernel(
    const float* __restrict__ qkv1,     // [b][1152][hw]
    const float* __restrict__ dww,      // [1152][9]
    float* __restrict__ gwin)
{
    __shared__ __align__(16) float h4[4][34 * HSTR];
    __shared__ float s_dww[144 * 9];
    __shared__ __align__(8) uint64_t mbar[4];

    const int tid  = threadIdx.x;
    const int tile = blockIdx.x;           // 0..63
    const int head = blockIdx.y;
    const int b    = blockIdx.z;
    const int tyb = tile >> 3, txb = tile & 7;
    const int y0 = tyb * 32 - 1, x0 = txb * 32 - 1;

    const int cs = x0 - 3;
    const int src_off = cs < 0 ? 0 : cs;
    const int dst_off = src_off - cs;
    const int cend = (cs + 40 > 256) ? 256 : (cs + 40);
    const uint32_t rowbytes = (uint32_t)(cend - src_off) * 4;
    const int r_lo = (y0 < 0) ? 1 : 0;
    const int r_hi = (y0 + 33 > 255) ? 32 : 33;
    const uint32_t expect = (uint32_t)(r_hi - r_lo + 1) * rowbytes;

    for (int e = tid; e < 144 * 9; e += 256) {
        const int l = e / 9, kk = e - l * 9;
        const int z = l / 48, cl = l - z * 48;
        s_dww[e] = dww[(size_t)(z * DIMC + head * CPH + cl) * 9 + kk];
    }
    for (int e = tid; e < 4 * 34 * HSTR; e += 256) (&h4[0][0])[e] = 0.f;
    if (tid < 4) MBARRIER_INIT(smem_u32(&mbar[tid]), 1);
    __syncthreads();
    FENCE_PROXY_ASYNC();

    const size_t bbase = (size_t)b * QKV_M * HW;
    const int wid = tid >> 5, lane = tid & 31;

    auto issue = [&](int ch) {
        const int st = ch & 3;
        const uint32_t mb = smem_u32(&mbar[st]);
        if (lane == 0) MBARRIER_EXPECT_TX(mb, expect);
        const int gc = (ch / 48) * DIMC + head * CPH + (ch % 48);
        const float* srcc = qkv1 + bbase + (size_t)gc * HW;
        const uint32_t dbase = smem_u32(&h4[st][0]);
        for (int r = lane; r < 34; r += 32) {
            if (r >= r_lo && r <= r_hi) {
                BULK_CPY(dbase + (uint32_t)(r * HSTR + dst_off) * 4,
                         srcc + (size_t)(y0 + r) * 256 + src_off,
                         rowbytes, mb);
            }
        }
    };
    if (wid == 0) { issue(0); issue(1); issue(2); }

    const int orow = tid >> 3;
    const int xq   = (tid & 7) * 4;
    const int wy_l = orow >> 3, wx_l = xq >> 3;
    const int win = (tyb * 4 + wy_l) * 32 + txb * 4 + wx_l;
    float* wbase = gwin + (((size_t)(b * HEADS + head) * 1024 + win) * 144) * 64
                 + (orow & 7) * 8 + (xq & 7);

#pragma unroll 1
    for (int ch = 0; ch < 144; ch++) {
        if (wid == 0 && ch + 3 < 144) issue(ch + 3);
        MBARRIER_WAIT_PARITY(smem_u32(&mbar[ch & 3]), (ch >> 2) & 1);

        const float* hb = h4[ch & 3] + orow * HSTR + xq + 3;
        const float* wp = s_dww + ch * 9;
        float w[9];
#pragma unroll
        for (int i = 0; i < 9; i++) w[i] = wp[i];
        float a[3][6];
#pragma unroll
        for (int dy = 0; dy < 3; dy++)
#pragma unroll
            for (int c = 0; c < 6; c++) a[dy][c] = hb[dy * HSTR + c];
        float4 o;
        o.x = a[0][0]*w[0] + a[0][1]*w[1] + a[0][2]*w[2]
            + a[1][0]*w[3] + a[1][1]*w[4] + a[1][2]*w[5]
            + a[2][0]*w[6] + a[2][1]*w[7] + a[2][2]*w[8];
        o.y = a[0][1]*w[0] + a[0][2]*w[1] + a[0][3]*w[2]
            + a[1][1]*w[3] + a[1][2]*w[4] + a[1][3]*w[5]
            + a[2][1]*w[6] + a[2][2]*w[7] + a[2][3]*w[8];
        o.z = a[0][2]*w[0] + a[0][3]*w[1] + a[0][4]*w[2]
            + a[1][2]*w[3] + a[1][3]*w[4] + a[1][4]*w[5]
            + a[2][2]*w[6] + a[2][3]*w[7] + a[2][4]*w[8];
        o.w = a[0][3]*w[0] + a[0][4]*w[1] + a[0][5]*w[2]
            + a[1][3]*w[3] + a[1][4]*w[4] + a[1][5]*w[5]
            + a[2][3]*w[6] + a[2][4]*w[7] + a[2][5]*w[8];
        *reinterpret_cast<float4*>(wbase + (size_t)ch * 64) = o;
        __syncthreads();
    }
}

// ---------------- window channel-attention ----------------------------------
// smem: s_qkv f32 144x68 | s_attn f32 48x50 | q/k bf16 hi/lo 4x[48][64] swizzled
#define SQ 68
#define S_ATTN_STRIDE 50
#define A_OFF_ATTN 9792                        // floats
#define QKB_OFF   48768                        // bytes: (9792+2400)*4
#define QKB_SZ    6144                         // bytes per [48][64] bf16 array
#define A_SMEM_BYTES (QKB_OFF + 4 * QKB_SZ)    // 73344

__global__ __launch_bounds__(256) void attn_kernel(
    const float* __restrict__ gwin,          // [(b*8+head)*1024+win][144][64]
    const float* __restrict__ temperature,
    __nv_bfloat16* __restrict__ out_hi,      // [b][hw][384]
    __nv_bfloat16* __restrict__ out_lo)
{
    extern __shared__ float sm[];
    float* s_qkv  = sm;                      // 144 x SQ
    float* s_attn = sm + A_OFF_ATTN;         // 48 x 50
    __shared__ __align__(8) uint64_t a_mbar;
    const uint32_t smb = smem_u32(sm);
    const uint32_t sqa = smb;
    const uint32_t qh_b = smb + QKB_OFF;                 // q_hi
    const uint32_t kh_b = smb + QKB_OFF + 2 * QKB_SZ;    // k_hi  (lo = +QKB_SZ)
    char* smc = reinterpret_cast<char*>(sm);

    const int tid  = threadIdx.x;
    const int win  = blockIdx.x;
    const int head = blockIdx.y;
    const int b    = blockIdx.z;
    const int wy = win >> 5, wx = win & 31;
    const int wid = tid >> 5, lane = tid & 31;

    // ---- bulk-copy the 144x64 f32 block ----
    if (tid == 0) MBARRIER_INIT(smem_u32(&a_mbar), 1);
    __syncthreads();
    const float* base = gwin + (((size_t)(b * HEADS + head) * 1024 + win) * 144) * 64;
    if (tid < 32) {
        const uint32_t mb = smem_u32(&a_mbar);
        if (tid == 0) MBARRIER_EXPECT_TX(mb, 144 * 256);
        for (int r = tid; r < 144; r += 32)
            BULK_CPY(sqa + (uint32_t)(r * SQ) * 4, base + (size_t)r * 64, 256, mb);
    }
    MBARRIER_WAIT_PARITY(smem_u32(&a_mbar), 0);

    const float temp = __ldg(&temperature[head]);

    // ---- L2 normalize q,k; emit bf16 hi/lo (swizzled 128B rows) ----
    {
        const int grp = tid >> 3;
        const int gl  = tid & 7;
#pragma unroll
        for (int it = 0; it < 3; it++) {
            const int r = grp + it * 32;
            float* rp = s_qkv + r * SQ + gl * 8;
            float4 v0 = *reinterpret_cast<float4*>(rp);
            float4 v1 = *reinterpret_cast<float4*>(rp + 4);
            float s = v0.x * v0.x + v0.y * v0.y + v0.z * v0.z + v0.w * v0.w
                    + v1.x * v1.x + v1.y * v1.y + v1.z * v1.z + v1.w * v1.w;
            s += __shfl_xor_sync(0xffffffffu, s, 1);
            s += __shfl_xor_sync(0xffffffffu, s, 2);
            s += __shfl_xor_sync(0xffffffffu, s, 4);
            const float inv = 1.f / fmaxf(sqrtf(s), 1e-12f);
            float f[8] = { v0.x * inv, v0.y * inv, v0.z * inv, v0.w * inv,
                           v1.x * inv, v1.y * inv, v1.z * inv, v1.w * inv };
            uint32_t hi[4], lo[4];
#pragma unroll
            for (int p = 0; p < 4; p++) {
                __nv_bfloat162 h2 = __floats2bfloat162_rn(f[2 * p], f[2 * p + 1]);
                hi[p] = *reinterpret_cast<uint32_t*>(&h2);
                __nv_bfloat162 l2 = __floats2bfloat162_rn(
                    f[2 * p]     - __bfloat162float(h2.x),
                    f[2 * p + 1] - __bfloat162float(h2.y));
                lo[p] = *reinterpret_cast<uint32_t*>(&l2);
            }
            const int rr = (r < 48) ? r : r - 48;
            const uint32_t bh = ((r < 48) ? (QKB_OFF) : (QKB_OFF + 2 * QKB_SZ)) + swz128r(rr, gl);
            *reinterpret_cast<uint4*>(smc + bh) = make_uint4(hi[0], hi[1], hi[2], hi[3]);
            *reinterpret_cast<uint4*>(smc + bh + QKB_SZ) = make_uint4(lo[0], lo[1], lo[2], lo[3]);
        }
    }
    __syncthreads();

    // ---- QK via HMMA: attn[48][48] = Q . K^T (3-term hi/lo), 6 warps ----
    if (wid < 6) {
        const int wm = (wid >> 1) * 16;      // 0,16,32
        const int wn = (wid & 1) * 24;       // 0,24
        float acc[3][4];
#pragma unroll
        for (int j = 0; j < 3; j++)
#pragma unroll
            for (int k = 0; k < 4; k++) acc[j][k] = 0.f;

        const int a_r  = wm + (lane & 7) + ((lane >> 3) & 1) * 8;
        const int a_cb = lane >> 4;
        const int b_r  = wn + (lane & 7) + ((lane >> 4) & 1) * 8;
        const int b_cb = (lane >> 3) & 1;
        const int b2_r = wn + 16 + (lane & 7);

#pragma unroll
        for (int k16 = 0; k16 < 4; k16++) {
            uint32_t ah[4], al[4], b4h[4], b4l[4], b2h[2], b2l[2];
            const uint32_t qa = qh_b + swz128r(a_r, k16 * 2 + a_cb);
            ldmx4(ah, qa); ldmx4(al, qa + QKB_SZ);
            const uint32_t ka = kh_b + swz128r(b_r, k16 * 2 + b_cb);
            ldmx4(b4h, ka); ldmx4(b4l, ka + QKB_SZ);
            const uint32_t k2 = kh_b + swz128r(b2_r, k16 * 2 + b_cb);
            ldmx2(b2h, k2); ldmx2(b2l, k2 + QKB_SZ);

            mma16816(acc[0], ah, b4h[0], b4h[1]);
            mma16816(acc[1], ah, b4h[2], b4h[3]);
            mma16816(acc[2], ah, b2h[0], b2h[1]);
            mma16816(acc[0], ah, b4l[0], b4l[1]);
            mma16816(acc[1], ah, b4l[2], b4l[3]);
            mma16816(acc[2], ah, b2l[0], b2l[1]);
            mma16816(acc[0], al, b4h[0], b4h[1]);
            mma16816(acc[1], al, b4h[2], b4h[3]);
            mma16816(acc[2], al, b2h[0], b2h[1]);
        }
        const int row = wm + (lane >> 2);
        const int colb = wn + (lane & 3) * 2;
#pragma unroll
        for (int j = 0; j < 3; j++) {
            const int col = colb + j * 8;
            *reinterpret_cast<float2*>(&s_attn[row * S_ATTN_STRIDE + col]) =
                make_float2(acc[j][0] * temp, acc[j][1] * temp);
            *reinterpret_cast<float2*>(&s_attn[(row + 8) * S_ATTN_STRIDE + col]) =
                make_float2(acc[j][2] * temp, acc[j][3] * temp);
        }
    }
    __syncthreads();

    // ---- softmax over d ----
    {
        for (int r = wid; r < 48; r += 8) {
            const float v0 = s_attn[r * S_ATTN_STRIDE + lane];
            const float v1 = (lane < 16) ? s_attn[r * S_ATTN_STRIDE + lane + 32] : -1e30f;
            float m = fmaxf(v0, v1);
#pragma unroll
            for (int off = 16; off; off >>= 1) m = fmaxf(m, __shfl_xor_sync(0xffffffffu, m, off));
            const float e0 = __expf(v0 - m);
            const float e1 = (lane < 16) ? __expf(v1 - m) : 0.f;
            float s = e0 + e1;
#pragma unroll
            for (int off = 16; off; off >>= 1) s += __shfl_xor_sync(0xffffffffu, s, off);
            const float inv = 1.f / s;
            s_attn[r * S_ATTN_STRIDE + lane] = e0 * inv;
            if (lane < 16) s_attn[r * S_ATTN_STRIDE + lane + 32] = e1 * inv;
        }
    }
    __syncthreads();

    // ---- out[c][n] = sum_d attn[c][d] * v[d][n] -> overwrite q rows --------
    float* s_out = s_qkv;
    {
        const int ty = tid >> 4, tx = tid & 15;
        float4 a0c = make_float4(0.f, 0.f, 0.f, 0.f);
        float4 a1c = a0c, a2c = a0c;
        const float* ar0 = s_attn + (ty * 3 + 0) * S_ATTN_STRIDE;
        const float* ar1 = s_attn + (ty * 3 + 1) * S_ATTN_STRIDE;
        const float* ar2 = s_attn + (ty * 3 + 2) * S_ATTN_STRIDE;
#pragma unroll 4
        for (int d = 0; d < 48; ++d) {
            const float a0 = ar0[d], a1 = ar1[d], a2 = ar2[d];
            const float4 v = *reinterpret_cast<const float4*>(&s_qkv[(96 + d) * SQ + tx * 4]);
            a0c.x += a0 * v.x; a0c.y += a0 * v.y; a0c.z += a0 * v.z; a0c.w += a0 * v.w;
            a1c.x += a1 * v.x; a1c.y += a1 * v.y; a1c.z += a1 * v.z; a1c.w += a1 * v.w;
            a2c.x += a2 * v.x; a2c.y += a2 * v.y; a2c.z += a2 * v.z; a2c.w += a2 * v.w;
        }
        __syncthreads();
        *reinterpret_cast<float4*>(&s_out[(ty * 3 + 0) * SQ + tx * 4]) = a0c;
        *reinterpret_cast<float4*>(&s_out[(ty * 3 + 1) * SQ + tx * 4]) = a1c;
        *reinterpret_cast<float4*>(&s_out[(ty * 3 + 2) * SQ + tx * 4]) = a2c;
    }
    __syncthreads();

    // ---- write bf16 hi/lo to [b][hw][384] ----
    for (int e = tid; e < 1536; e += 256) {
        const int c2 = e % 24;
        const int n  = e / 24;
        const int c  = c2 * 2;
        const float va = s_qkv[c * SQ + n];
        const float vb = s_qkv[(c + 1) * SQ + n];
        const int yy = n >> 3, xx = n & 7;
        const int hw = ((wy * 8 + yy) << 8) + wx * 8 + xx;
        const size_t off = ((size_t)b * HW + hw) * DIMC + head * CPH + c;
        const __nv_bfloat16 ha = __float2bfloat16(va);
        const __nv_bfloat16 hb = __float2bfloat16(vb);
        __nv_bfloat162 hi2, lo2;
        hi2.x = ha; hi2.y = hb;
        lo2.x = __float2bfloat16(va - __bfloat162float(ha));
        lo2.y = __float2bfloat16(vb - __bfloat162float(hb));
        *reinterpret_cast<__nv_bfloat162*>(&out_hi[off]) = hi2;
        *reinterpret_cast<__nv_bfloat162*>(&out_lo[off]) = lo2;
    }
}

// ---------------- launch ----------------------------------------------------
extern "C" void kernel_launch(void* const* d_in, const int* in_sizes, int n_in,
                              void* d_out, int out_size)
{
    const float* x      = (const float*)d_in[0];
    const float* qkv_w  = (const float*)d_in[1];
    const float* dw_w   = (const float*)d_in[2];
    const float* temp   = (const float*)d_in[3];
    const float* proj_w = (const float*)d_in[4];
    const float* proj_b = (const float*)d_in[5];
    float* out = (float*)d_out;

    float *qkv_buf, *win_buf;
    __nv_bfloat16 *xt_hi, *xt_lo, *at_hi, *at_lo, *wq_hi, *wq_lo, *wp_hi, *wp_lo;
    cudaGetSymbolAddress((void**)&qkv_buf, g_qkv);
    cudaGetSymbolAddress((void**)&win_buf, g_win);
    cudaGetSymbolAddress((void**)&xt_hi, g_xt_hi);
    cudaGetSymbolAddress((void**)&xt_lo, g_xt_lo);
    cudaGetSymbolAddress((void**)&at_hi, g_at_hi);
    cudaGetSymbolAddress((void**)&at_lo, g_at_lo);
    cudaGetSymbolAddress((void**)&wq_hi, g_wq_hi);
    cudaGetSymbolAddress((void**)&wq_lo, g_wq_lo);
    cudaGetSymbolAddress((void**)&wp_hi, g_wp_hi);
    cudaGetSymbolAddress((void**)&wp_lo, g_wp_lo);

    cudaFuncSetAttribute(attn_kernel, cudaFuncAttributeMaxDynamicSharedMemorySize, A_SMEM_BYTES);
    cudaFuncSetAttribute(hmma_gemm<0>, cudaFuncAttributeMaxDynamicSharedMemorySize, HG_SMEM);
    cudaFuncSetAttribute(hmma_gemm<1>, cudaFuncAttributeMaxDynamicSharedMemorySize, HG_SMEM);

    // weight splits
    split_w<<<(QKV_M * DIMC + 255) / 256, 256>>>(qkv_w, wq_hi, wq_lo, QKV_M * DIMC);
    split_w<<<(DIMC * DIMC + 255) / 256, 256>>>(proj_w, wp_hi, wp_lo, DIMC * DIMC);

    // x -> transposed hi/lo bf16 [b][hw][384]
    transpose_split<<<dim3(HW / 32, DIMC / 32, BATCH), 256>>>(x, xt_hi, xt_lo, DIMC, HW);

    // qkv = W_qkv . x   -> g_qkv [b][1152][hw] f32
    hmma_gemm<0><<<dim3(QKV_M / 128, HW / 128, BATCH), 256, HG_SMEM>>>(
        wq_hi, wq_lo, xt_hi, xt_lo, qkv_buf, QKV_M, HW, DIMC, nullptr);

    // depthwise 3x3 -> window-major layout
    dwconv_kernel<<<dim3(64, HEADS, BATCH), 256>>>(qkv_buf, dw_w, win_buf);

    // window channel attention -> bf16 hi/lo [b][hw][384]
    attn_kernel<<<dim3(1024, HEADS, BATCH), 256, A_SMEM_BYTES>>>(
        win_buf, temp, at_hi, at_lo);

    // out = W_proj . att + b
    hmma_gemm<1><<<dim3(DIMC / 128, HW / 128, BATCH), 256, HG_SMEM>>>(
        wp_hi, wp_lo, at_hi, at_lo, out, DIMC, HW, DIMC, proj_b);
}